// round 3
// baseline (speedup 1.0000x reference)
#include <cuda_runtime.h>
#include <cuda_bf16.h>

// ---------------------------------------------------------------------------
// GroupLocalAttention, restructured:
//   1) QKV_all[p,1152] = feats[p,:] @ Wqkv^T          (dense GEMM, per point)
//   2) per group: gather q,k,v rows, masked softmax attention,
//      scatter-add pre-projection outputs (mask-weighted) + counts
//   3) avg = acc / max(cnt,1)  (bf16)
//   4) out = feats + gamma * (avg @ Wproj^T + b_proj * [cnt>0])  (dense GEMM)
// grouping_idx dtype is sniffed at runtime (int32 vs int64) — JAX default
// config downcasts jnp.int64 to int32.
// ---------------------------------------------------------------------------

#define NPTS 65536      // B * N_MAX
#define CDIM 384
#define QKVD 1152
#define NGRP 4096       // B * G
#define KG   32
#define NH   6
#define DHD  64

// scratch (static device allocations — no cudaMalloc)
__device__ __align__(16) __nv_bfloat16 g_feats_bf[(size_t)NPTS * CDIM];
__device__ __align__(16) __nv_bfloat16 g_qkv[(size_t)NPTS * QKVD];
__device__ __align__(16) float         g_acc[(size_t)NPTS * CDIM];
__device__ __align__(16) float         g_cnt[NPTS];
__device__ __align__(16) __nv_bfloat16 g_avg_bf[(size_t)NPTS * CDIM];
__device__ __align__(16) __nv_bfloat16 g_wqkv_bf[QKVD * CDIM];
__device__ __align__(16) __nv_bfloat16 g_wproj_bf[CDIM * CDIM];
__device__ int g_is64;

// ---------------------------------------------------------------------------
// prep kernels
// ---------------------------------------------------------------------------
__global__ void k_sniff(const int* __restrict__ w) {
    if (threadIdx.x == 0 && blockIdx.x == 0) {
        int all0 = 1;
        for (int i = 1; i < 64; i += 2) all0 &= (w[i] == 0 || w[i] == -1);
        g_is64 = all0;
    }
}

__global__ void k_zero() {
    int i = blockIdx.x * blockDim.x + threadIdx.x;
    const int nAcc4 = NPTS * CDIM / 4;
    const int nCnt4 = NPTS / 4;
    if (i < nAcc4) {
        ((float4*)g_acc)[i] = make_float4(0.f, 0.f, 0.f, 0.f);
    } else if (i < nAcc4 + nCnt4) {
        ((float4*)g_cnt)[i - nAcc4] = make_float4(0.f, 0.f, 0.f, 0.f);
    }
}

__global__ void k_conv_feats(const float* __restrict__ src) {
    int i = blockIdx.x * blockDim.x + threadIdx.x;
    const int n4 = NPTS * CDIM / 4;
    if (i < n4) {
        float4 v = ((const float4*)src)[i];
        ((__nv_bfloat162*)g_feats_bf)[2 * i]     = __floats2bfloat162_rn(v.x, v.y);
        ((__nv_bfloat162*)g_feats_bf)[2 * i + 1] = __floats2bfloat162_rn(v.z, v.w);
    }
}

__global__ void k_conv_w(const float* __restrict__ wqkv, const float* __restrict__ wproj) {
    int i = blockIdx.x * blockDim.x + threadIdx.x;
    const int n1 = QKVD * CDIM / 4;
    const int n2 = CDIM * CDIM / 4;
    if (i < n1) {
        float4 v = ((const float4*)wqkv)[i];
        ((__nv_bfloat162*)g_wqkv_bf)[2 * i]     = __floats2bfloat162_rn(v.x, v.y);
        ((__nv_bfloat162*)g_wqkv_bf)[2 * i + 1] = __floats2bfloat162_rn(v.z, v.w);
    } else if (i < n1 + n2) {
        int j = i - n1;
        float4 v = ((const float4*)wproj)[j];
        ((__nv_bfloat162*)g_wproj_bf)[2 * j]     = __floats2bfloat162_rn(v.x, v.y);
        ((__nv_bfloat162*)g_wproj_bf)[2 * j + 1] = __floats2bfloat162_rn(v.z, v.w);
    }
}

__global__ void k_avg() {
    int i = blockIdx.x * blockDim.x + threadIdx.x;  // float4 index
    const int n4 = NPTS * CDIM / 4;
    if (i < n4) {
        int row = (i * 4) / CDIM;
        float r = 1.f / fmaxf(g_cnt[row], 1.f);
        float4 v = ((const float4*)g_acc)[i];
        ((__nv_bfloat162*)g_avg_bf)[2 * i]     = __floats2bfloat162_rn(v.x * r, v.y * r);
        ((__nv_bfloat162*)g_avg_bf)[2 * i + 1] = __floats2bfloat162_rn(v.z * r, v.w * r);
    }
}

// ---------------------------------------------------------------------------
// bf16 GEMM, C[M,N] = A[M,384] * B[N,384]^T
// 128x128 CTA tile, K-tile 32, cp.async double buffer, mma.sync m16n8k16
// smem: 2 stages * (A 128x40 + B 128x40) bf16 = 40960 B  (<48KB, no opt-in)
// EPI=false: A=g_feats_bf, B=g_wqkv_bf, C -> g_qkv (bf16, ldc=1152)
// EPI=true:  A=g_avg_bf,  B=g_wproj_bf, fused final epilogue -> out (f32)
// ---------------------------------------------------------------------------
template <bool EPI>
__global__ void __launch_bounds__(256) gemm_k(const float* __restrict__ feats,
                                              const float* __restrict__ gamma,
                                              const float* __restrict__ bproj,
                                              float* __restrict__ outp) {
    const __nv_bfloat16* __restrict__ A  = EPI ? g_avg_bf : g_feats_bf;
    const __nv_bfloat16* __restrict__ Bw = EPI ? g_wproj_bf : g_wqkv_bf;
    constexpr int LDC = EPI ? CDIM : QKVD;

    extern __shared__ __nv_bfloat16 smemg[];
    constexpr int LDS_ = 40;           // padded row stride (32 -> 40 elems)
    constexpr int TSZ = 128 * LDS_;    // one tile: 5120 elems = 10240 B

    const int m0 = blockIdx.y * 128;
    const int n0 = blockIdx.x * 128;
    const int tid = threadIdx.x;
    const int warp = tid >> 5, lane = tid & 31;
    const int wm = warp & 3, wn = warp >> 2;     // 4x2 warp grid
    const int g = lane >> 2, q = lane & 3;

    const int lr  = tid >> 1;        // load row 0..127
    const int lc0 = (tid & 1) * 2;   // chunk base (4 x 16B chunks per 64B row)

    auto load_stage = [&](int kt, int stage) {
        __nv_bfloat16* sA = smemg + stage * 2 * TSZ;
        __nv_bfloat16* sB = sA + TSZ;
        size_t gA = __cvta_generic_to_global(A  + (size_t)(m0 + lr) * CDIM + kt * 32);
        size_t gB = __cvta_generic_to_global(Bw + (size_t)(n0 + lr) * CDIM + kt * 32);
        unsigned dA = (unsigned)__cvta_generic_to_shared(sA + lr * LDS_);
        unsigned dB = (unsigned)__cvta_generic_to_shared(sB + lr * LDS_);
#pragma unroll
        for (int i = 0; i < 2; i++) {
            int ch = lc0 + i;
            asm volatile("cp.async.cg.shared.global [%0], [%1], 16;\n"
                         :: "r"(dA + ch * 16), "l"(gA + ch * 16));
            asm volatile("cp.async.cg.shared.global [%0], [%1], 16;\n"
                         :: "r"(dB + ch * 16), "l"(gB + ch * 16));
        }
    };

    float acc[2][8][4];
#pragma unroll
    for (int ti = 0; ti < 2; ti++)
#pragma unroll
        for (int tj = 0; tj < 8; tj++)
#pragma unroll
            for (int r = 0; r < 4; r++) acc[ti][tj][r] = 0.f;

    load_stage(0, 0);
    asm volatile("cp.async.commit_group;\n");

    constexpr int KT = CDIM / 32;  // 12
    for (int kt = 0; kt < KT; kt++) {
        if (kt + 1 < KT) {
            load_stage(kt + 1, (kt + 1) & 1);
            asm volatile("cp.async.commit_group;\n");
            asm volatile("cp.async.wait_group 1;\n");
        } else {
            asm volatile("cp.async.wait_group 0;\n");
        }
        __syncthreads();
        const __nv_bfloat16* sA = smemg + (kt & 1) * 2 * TSZ;
        const __nv_bfloat16* sB = sA + TSZ;
#pragma unroll
        for (int ks = 0; ks < 2; ks++) {
            const int k0 = ks * 16;
            unsigned af[2][4];
#pragma unroll
            for (int ti = 0; ti < 2; ti++) {
                int R = wm * 32 + ti * 16;
                af[ti][0] = *(const unsigned*)(sA + (R + g)     * LDS_ + k0 + 2 * q);
                af[ti][1] = *(const unsigned*)(sA + (R + g + 8) * LDS_ + k0 + 2 * q);
                af[ti][2] = *(const unsigned*)(sA + (R + g)     * LDS_ + k0 + 2 * q + 8);
                af[ti][3] = *(const unsigned*)(sA + (R + g + 8) * LDS_ + k0 + 2 * q + 8);
            }
            unsigned bfr[8][2];
#pragma unroll
            for (int tj = 0; tj < 8; tj++) {
                int Cn = wn * 64 + tj * 8 + g;
                bfr[tj][0] = *(const unsigned*)(sB + Cn * LDS_ + k0 + 2 * q);
                bfr[tj][1] = *(const unsigned*)(sB + Cn * LDS_ + k0 + 2 * q + 8);
            }
#pragma unroll
            for (int ti = 0; ti < 2; ti++)
#pragma unroll
                for (int tj = 0; tj < 8; tj++)
                    asm volatile(
                        "mma.sync.aligned.m16n8k16.row.col.f32.bf16.bf16.f32 "
                        "{%0,%1,%2,%3},{%4,%5,%6,%7},{%8,%9},{%0,%1,%2,%3};\n"
                        : "+f"(acc[ti][tj][0]), "+f"(acc[ti][tj][1]),
                          "+f"(acc[ti][tj][2]), "+f"(acc[ti][tj][3])
                        : "r"(af[ti][0]), "r"(af[ti][1]), "r"(af[ti][2]), "r"(af[ti][3]),
                          "r"(bfr[tj][0]), "r"(bfr[tj][1]));
        }
        __syncthreads();
    }

    // epilogue
#pragma unroll
    for (int ti = 0; ti < 2; ti++) {
        int r0 = m0 + wm * 32 + ti * 16 + g;
#pragma unroll
        for (int tj = 0; tj < 8; tj++) {
            int col = n0 + wn * 64 + tj * 8 + 2 * q;
            if (!EPI) {
                *(__nv_bfloat162*)(g_qkv + (size_t)r0 * LDC + col) =
                    __floats2bfloat162_rn(acc[ti][tj][0], acc[ti][tj][1]);
                *(__nv_bfloat162*)(g_qkv + (size_t)(r0 + 8) * LDC + col) =
                    __floats2bfloat162_rn(acc[ti][tj][2], acc[ti][tj][3]);
            } else {
                float ga0 = gamma[col], ga1 = gamma[col + 1];
                float bp0 = bproj[col], bp1 = bproj[col + 1];
                {
                    float flag = g_cnt[r0] > 0.5f ? 1.f : 0.f;
                    size_t o = (size_t)r0 * LDC + col;
                    outp[o]     = feats[o]     + ga0 * (acc[ti][tj][0] + bp0 * flag);
                    outp[o + 1] = feats[o + 1] + ga1 * (acc[ti][tj][1] + bp1 * flag);
                }
                {
                    float flag = g_cnt[r0 + 8] > 0.5f ? 1.f : 0.f;
                    size_t o = (size_t)(r0 + 8) * LDC + col;
                    outp[o]     = feats[o]     + ga0 * (acc[ti][tj][2] + bp0 * flag);
                    outp[o + 1] = feats[o + 1] + ga1 * (acc[ti][tj][3] + bp1 * flag);
                }
            }
        }
    }
}

// ---------------------------------------------------------------------------
// per-group attention + scatter. 1 CTA per group, 128 threads.
// smem: q/k/v 32x68 f32 + probs 32x36 f32 + idx/mask = ~31KB
// Per-head outputs scatter straight from registers (atomicAdd).
// ---------------------------------------------------------------------------
__global__ void __launch_bounds__(128) attn_k(const int* __restrict__ gidxw,
                                              const float* __restrict__ gmask) {
    extern __shared__ float sm[];
    float* qs  = sm;                  // 32*68
    float* ksm = qs  + 32 * 68;       // 32*68
    float* vsm = ksm + 32 * 68;       // 32*68
    float* pr  = vsm + 32 * 68;       // 32*36
    int*   Pp  = (int*)(pr + 32 * 36);   // 32
    float* mm  = (float*)(Pp + 32);      // 32

    const int tid = threadIdx.x;
    const int base = blockIdx.x * KG;
    const int bb = blockIdx.x >> 9;  // batch = group / 512

    if (tid < 32) {
        int slot = base + tid;
        int p = g_is64 ? gidxw[2 * slot] : gidxw[slot];  // int64 low word or int32
        p = p < 0 ? 0 : (p > 8191 ? 8191 : p);
        Pp[tid] = bb * 8192 + p;
        mm[tid] = gmask[slot];
    }
    __syncthreads();

    const int qi = tid >> 2, quar = tid & 3;
    const int grow = tid >> 2, gc0 = tid & 3;

    const int   myP = Pp[qi];
    const float myW = mm[qi];

    for (int h = 0; h < NH; h++) {
        // gather q,k,v rows for this head (bf16 -> f32 smem)
        const size_t rowbase = (size_t)Pp[grow] * QKVD + h * DHD;
#pragma unroll
        for (int sec = 0; sec < 3; sec++) {
            float* dst = (sec == 0) ? qs : (sec == 1) ? ksm : vsm;
            const __nv_bfloat16* src = g_qkv + rowbase + sec * CDIM;
#pragma unroll
            for (int half = 0; half < 2; half++) {
                int ch = gc0 + half * 4;
                uint4 u = *(const uint4*)(src + ch * 8);
                const __nv_bfloat162* pb = (const __nv_bfloat162*)&u;
                float* d = dst + grow * 68 + ch * 8;
#pragma unroll
                for (int j = 0; j < 4; j++) {
                    float2 f = __bfloat1622float2(pb[j]);
                    *(float2*)(d + 2 * j) = f;
                }
            }
        }
        __syncthreads();

        // scores: thread (qi, quar) does 8 keys
        float s[8];
#pragma unroll
        for (int j = 0; j < 8; j++) s[j] = 0.f;
#pragma unroll
        for (int d4 = 0; d4 < 16; d4++) {
            float4 qv = *(const float4*)(qs + qi * 68 + d4 * 4);
#pragma unroll
            for (int j = 0; j < 8; j++) {
                float4 kv = *(const float4*)(ksm + (quar * 8 + j) * 68 + d4 * 4);
                s[j] += qv.x * kv.x + qv.y * kv.y + qv.z * kv.z + qv.w * kv.w;
            }
        }
        float mx = -3e38f;
#pragma unroll
        for (int j = 0; j < 8; j++) {
            s[j] = s[j] * 0.125f + (mm[quar * 8 + j] > 0.f ? 0.f : -1e9f);
            mx = fmaxf(mx, s[j]);
        }
        mx = fmaxf(mx, __shfl_xor_sync(0xffffffffu, mx, 1));
        mx = fmaxf(mx, __shfl_xor_sync(0xffffffffu, mx, 2));
        float ssum = 0.f;
#pragma unroll
        for (int j = 0; j < 8; j++) { s[j] = __expf(s[j] - mx); ssum += s[j]; }
        ssum += __shfl_xor_sync(0xffffffffu, ssum, 1);
        ssum += __shfl_xor_sync(0xffffffffu, ssum, 2);
        float rinv = 1.f / ssum;
#pragma unroll
        for (int j = 0; j < 8; j++) pr[qi * 36 + quar * 8 + j] = s[j] * rinv;
        __syncthreads();

        // out = attn @ v : thread (qi, quar) does 16 cols of head h
        float4 o[4];
#pragma unroll
        for (int c = 0; c < 4; c++) o[c] = make_float4(0.f, 0.f, 0.f, 0.f);
        for (int kj = 0; kj < 32; kj++) {
            float a = pr[qi * 36 + kj];
#pragma unroll
            for (int c = 0; c < 4; c++) {
                float4 vv = *(const float4*)(vsm + kj * 68 + quar * 16 + c * 4);
                o[c].x += a * vv.x; o[c].y += a * vv.y;
                o[c].z += a * vv.z; o[c].w += a * vv.w;
            }
        }
        // scatter-add this head's output (mask-weighted) straight from regs
        if (myW != 0.f) {
            float* dst = g_acc + (size_t)myP * CDIM + h * DHD + quar * 16;
#pragma unroll
            for (int c = 0; c < 4; c++) {
                atomicAdd(dst + c * 4 + 0, o[c].x * myW);
                atomicAdd(dst + c * 4 + 1, o[c].y * myW);
                atomicAdd(dst + c * 4 + 2, o[c].z * myW);
                atomicAdd(dst + c * 4 + 3, o[c].w * myW);
            }
        }
        __syncthreads();
    }

    if (tid < 32 && mm[tid] != 0.f) atomicAdd(g_cnt + Pp[tid], mm[tid]);
}

// ---------------------------------------------------------------------------
// launch — ONLY kernel launches (graph-capture safe, no attribute APIs)
// ---------------------------------------------------------------------------
extern "C" void kernel_launch(void* const* d_in, const int* in_sizes, int n_in,
                              void* d_out, int out_size) {
    const float* feats = (const float*)d_in[0];
    const int*   gidxw = (const int*)d_in[1];
    const float* gmask = (const float*)d_in[2];
    const float* wqkv  = (const float*)d_in[3];
    const float* wproj = (const float*)d_in[4];
    const float* bproj = (const float*)d_in[5];
    const float* gamma = (const float*)d_in[6];
    float*       outp  = (float*)d_out;

    const int gemm_smem = 2 * 2 * 128 * 40 * 2;                      // 40960 B
    const int attn_smem = (32 * 68 * 3 + 32 * 36 + 64) * 4;          // 30976 B

    k_sniff<<<1, 32>>>(gidxw);

    const int nZero = NPTS * CDIM / 4 + NPTS / 4;
    k_zero<<<(nZero + 255) / 256, 256>>>();

    const int nFeat4 = NPTS * CDIM / 4;
    k_conv_feats<<<(nFeat4 + 255) / 256, 256>>>(feats);

    const int nW4 = QKVD * CDIM / 4 + CDIM * CDIM / 4;
    k_conv_w<<<(nW4 + 255) / 256, 256>>>(wqkv, wproj);

    gemm_k<false><<<dim3(QKVD / 128, NPTS / 128), 256, gemm_smem>>>(nullptr, nullptr, nullptr, nullptr);

    attn_k<<<NGRP, 128, attn_smem>>>(gidxw, gmask);

    k_avg<<<(nFeat4 + 255) / 256, 256>>>();

    gemm_k<true><<<dim3(CDIM / 128, NPTS / 128), 256, gemm_smem>>>(feats, gamma, bproj, outp);
}

// round 5
// speedup vs baseline: 1.0460x; 1.0460x over previous
#include <cuda_runtime.h>
#include <cuda_bf16.h>
#include <cstdint>

// ---------------------------------------------------------------------------
// GroupLocalAttention, restructured (sm_100 baseline ISA: mma.sync + ldmatrix):
//   1) QKV_all[p,1152] = feats[p,:] @ Wqkv^T       (bf16 mma GEMM, per point)
//   2) per group: gather q,k,v rows, masked softmax attention,
//      scatter-add pre-projection outputs (bf16x2 atomics) + counts
//   3) avg = acc / max(cnt,1)  (bf16)
//   4) out = feats + gamma*(avg @ Wproj^T + b_proj*[cnt>0])  (bf16 mma GEMM)
// ---------------------------------------------------------------------------

#define NPTS 65536      // B * N_MAX
#define CDIM 384
#define QKVD 1152
#define NGRP 4096       // B * G
#define KG   32
#define NH   6
#define DHD  64

// scratch (static device allocations — no cudaMalloc)
__device__ __align__(16) __nv_bfloat16  g_feats_bf[(size_t)NPTS * CDIM];
__device__ __align__(16) __nv_bfloat16  g_qkv[(size_t)NPTS * QKVD];
__device__ __align__(16) __nv_bfloat162 g_acc2[(size_t)NPTS * CDIM / 2];
__device__ __align__(16) float          g_cnt[NPTS];
__device__ __align__(16) __nv_bfloat16  g_avg_bf[(size_t)NPTS * CDIM];
__device__ __align__(16) __nv_bfloat16  g_wqkv_bf[QKVD * CDIM];
__device__ __align__(16) __nv_bfloat16  g_wproj_bf[CDIM * CDIM];
__device__ int g_is64;

// ---------------------------------------------------------------------------
// prep kernels
// ---------------------------------------------------------------------------
__global__ void k_sniff(const int* __restrict__ w) {
    if (threadIdx.x == 0 && blockIdx.x == 0) {
        int all0 = 1;
        for (int i = 1; i < 64; i += 2) all0 &= (w[i] == 0 || w[i] == -1);
        g_is64 = all0;
    }
}

__global__ void k_zero() {
    int i = blockIdx.x * blockDim.x + threadIdx.x;
    const int nAccV = NPTS * CDIM / 8;   // float4 units over bf16 acc
    const int nCntV = NPTS / 4;
    if (i < nAccV) {
        ((float4*)g_acc2)[i] = make_float4(0.f, 0.f, 0.f, 0.f);
    } else if (i < nAccV + nCntV) {
        ((float4*)g_cnt)[i - nAccV] = make_float4(0.f, 0.f, 0.f, 0.f);
    }
}

__global__ void k_conv_feats(const float* __restrict__ src) {
    int i = blockIdx.x * blockDim.x + threadIdx.x;
    const int n4 = NPTS * CDIM / 4;
    if (i < n4) {
        float4 v = ((const float4*)src)[i];
        ((__nv_bfloat162*)g_feats_bf)[2 * i]     = __floats2bfloat162_rn(v.x, v.y);
        ((__nv_bfloat162*)g_feats_bf)[2 * i + 1] = __floats2bfloat162_rn(v.z, v.w);
    }
}

__global__ void k_conv_w(const float* __restrict__ wqkv, const float* __restrict__ wproj) {
    int i = blockIdx.x * blockDim.x + threadIdx.x;
    const int n1 = QKVD * CDIM / 4;
    const int n2 = CDIM * CDIM / 4;
    if (i < n1) {
        float4 v = ((const float4*)wqkv)[i];
        ((__nv_bfloat162*)g_wqkv_bf)[2 * i]     = __floats2bfloat162_rn(v.x, v.y);
        ((__nv_bfloat162*)g_wqkv_bf)[2 * i + 1] = __floats2bfloat162_rn(v.z, v.w);
    } else if (i < n1 + n2) {
        int j = i - n1;
        float4 v = ((const float4*)wproj)[j];
        ((__nv_bfloat162*)g_wproj_bf)[2 * j]     = __floats2bfloat162_rn(v.x, v.y);
        ((__nv_bfloat162*)g_wproj_bf)[2 * j + 1] = __floats2bfloat162_rn(v.z, v.w);
    }
}

__global__ void k_avg() {
    int i = blockIdx.x * blockDim.x + threadIdx.x;  // uint4 = 8 bf16
    const int n = NPTS * CDIM / 8;
    if (i < n) {
        int row = (i * 8) / CDIM;
        float sc = 1.f / fmaxf(g_cnt[row], 1.f);
        uint4 u = ((const uint4*)g_acc2)[i];
        uint32_t w[4] = {u.x, u.y, u.z, u.w};
#pragma unroll
        for (int j = 0; j < 4; j++) {
            float2 f = __bfloat1622float2(*(__nv_bfloat162*)&w[j]);
            __nv_bfloat162 h = __floats2bfloat162_rn(f.x * sc, f.y * sc);
            w[j] = *(uint32_t*)&h;
        }
        ((uint4*)g_avg_bf)[i] = make_uint4(w[0], w[1], w[2], w[3]);
    }
}

// ---------------------------------------------------------------------------
// ldmatrix helper: x4, non-transposed, b16
// ---------------------------------------------------------------------------
__device__ __forceinline__ void ldsm4(unsigned& x, unsigned& y, unsigned& z, unsigned& w,
                                      const void* p) {
    unsigned a = (unsigned)__cvta_generic_to_shared(p);
    asm volatile("ldmatrix.sync.aligned.m8n8.x4.shared.b16 {%0,%1,%2,%3}, [%4];"
                 : "=r"(x), "=r"(y), "=r"(z), "=r"(w) : "r"(a));
}

// ---------------------------------------------------------------------------
// bf16 GEMM, C[M,N] = A[M,384] * B[N,384]^T
// 128x128 CTA tile, K-tile 32, cp.async double buffer, mma.sync m16n8k16,
// ldmatrix.x4 fragment loads (conflict-free with 80B padded rows).
// smem: 2 stages * (A 128x40 + B 128x40) bf16 = 40960 B (<48KB)
// EPI=false: A=g_feats_bf, B=g_wqkv_bf, C -> g_qkv (bf16, ldc=1152)
// EPI=true:  A=g_avg_bf,  B=g_wproj_bf, fused final epilogue -> out (f32)
// ---------------------------------------------------------------------------
template <bool EPI>
__global__ void __launch_bounds__(256) gemm_k(const float* __restrict__ feats,
                                              const float* __restrict__ gamma,
                                              const float* __restrict__ bproj,
                                              float* __restrict__ outp) {
    const __nv_bfloat16* __restrict__ A  = EPI ? g_avg_bf : g_feats_bf;
    const __nv_bfloat16* __restrict__ Bw = EPI ? g_wproj_bf : g_wqkv_bf;
    constexpr int LDC = EPI ? CDIM : QKVD;

    extern __shared__ __nv_bfloat16 smemg[];
    constexpr int LDS_ = 40;           // padded row stride (32 -> 40 elems, 80B)
    constexpr int TSZ = 128 * LDS_;    // one tile: 5120 elems = 10240 B

    const int m0 = blockIdx.y * 128;
    const int n0 = blockIdx.x * 128;
    const int tid = threadIdx.x;
    const int warp = tid >> 5, lane = tid & 31;
    const int wm = warp & 3, wn = warp >> 2;     // 4x2 warp grid
    const int g = lane >> 2, q = lane & 3;

    const int lr  = tid >> 1;        // load row 0..127
    const int lc0 = (tid & 1) * 2;   // chunk base (4 x 16B chunks per 64B row)

    // ldmatrix per-lane source row/col within a 16x16 tile
    const int lm_r = lane & 15;          // row within tile
    const int lm_c = (lane >> 4) * 8;    // 0 or 8 (k offset)

    auto load_stage = [&](int kt, int stage) {
        __nv_bfloat16* sA = smemg + stage * 2 * TSZ;
        __nv_bfloat16* sB = sA + TSZ;
        size_t gA = __cvta_generic_to_global(A  + (size_t)(m0 + lr) * CDIM + kt * 32);
        size_t gB = __cvta_generic_to_global(Bw + (size_t)(n0 + lr) * CDIM + kt * 32);
        unsigned dA = (unsigned)__cvta_generic_to_shared(sA + lr * LDS_);
        unsigned dB = (unsigned)__cvta_generic_to_shared(sB + lr * LDS_);
#pragma unroll
        for (int i = 0; i < 2; i++) {
            int ch = lc0 + i;
            asm volatile("cp.async.cg.shared.global [%0], [%1], 16;\n"
                         :: "r"(dA + ch * 16), "l"(gA + ch * 16));
            asm volatile("cp.async.cg.shared.global [%0], [%1], 16;\n"
                         :: "r"(dB + ch * 16), "l"(gB + ch * 16));
        }
    };

    float acc[2][8][4];
#pragma unroll
    for (int ti = 0; ti < 2; ti++)
#pragma unroll
        for (int tj = 0; tj < 8; tj++)
#pragma unroll
            for (int r = 0; r < 4; r++) acc[ti][tj][r] = 0.f;

    load_stage(0, 0);
    asm volatile("cp.async.commit_group;\n");

    constexpr int KT = CDIM / 32;  // 12
    for (int kt = 0; kt < KT; kt++) {
        if (kt + 1 < KT) {
            load_stage(kt + 1, (kt + 1) & 1);
            asm volatile("cp.async.commit_group;\n");
            asm volatile("cp.async.wait_group 1;\n");
        } else {
            asm volatile("cp.async.wait_group 0;\n");
        }
        __syncthreads();
        const __nv_bfloat16* sA = smemg + (kt & 1) * 2 * TSZ;
        const __nv_bfloat16* sB = sA + TSZ;
#pragma unroll
        for (int ks = 0; ks < 2; ks++) {
            const int k0 = ks * 16;
            // A fragments: 2 tiles of 16x16 via ldmatrix.x4
            unsigned af[2][4];
#pragma unroll
            for (int ti = 0; ti < 2; ti++) {
                int R = wm * 32 + ti * 16;
                ldsm4(af[ti][0], af[ti][1], af[ti][2], af[ti][3],
                      sA + (R + lm_r) * LDS_ + k0 + lm_c);
            }
            // B fragments: 4 pairs of n8 tiles (16 n-rows each) via ldmatrix.x4
            unsigned bfr[8][2];
#pragma unroll
            for (int pr2 = 0; pr2 < 4; pr2++) {
                int Cn0 = wn * 64 + pr2 * 16;
                unsigned x, y, z, w;
                ldsm4(x, y, z, w, sB + (Cn0 + lm_r) * LDS_ + k0 + lm_c);
                bfr[2 * pr2][0]     = x;  // n0-7,  k0-7
                bfr[2 * pr2][1]     = z;  // n0-7,  k8-15
                bfr[2 * pr2 + 1][0] = y;  // n8-15, k0-7
                bfr[2 * pr2 + 1][1] = w;  // n8-15, k8-15
            }
#pragma unroll
            for (int ti = 0; ti < 2; ti++)
#pragma unroll
                for (int tj = 0; tj < 8; tj++)
                    asm volatile(
                        "mma.sync.aligned.m16n8k16.row.col.f32.bf16.bf16.f32 "
                        "{%0,%1,%2,%3},{%4,%5,%6,%7},{%8,%9},{%0,%1,%2,%3};\n"
                        : "+f"(acc[ti][tj][0]), "+f"(acc[ti][tj][1]),
                          "+f"(acc[ti][tj][2]), "+f"(acc[ti][tj][3])
                        : "r"(af[ti][0]), "r"(af[ti][1]), "r"(af[ti][2]), "r"(af[ti][3]),
                          "r"(bfr[tj][0]), "r"(bfr[tj][1]));
        }
        __syncthreads();
    }

    // epilogue
#pragma unroll
    for (int ti = 0; ti < 2; ti++) {
        int r0 = m0 + wm * 32 + ti * 16 + g;
#pragma unroll
        for (int tj = 0; tj < 8; tj++) {
            int col = n0 + wn * 64 + tj * 8 + 2 * q;
            if (!EPI) {
                *(__nv_bfloat162*)(g_qkv + (size_t)r0 * LDC + col) =
                    __floats2bfloat162_rn(acc[ti][tj][0], acc[ti][tj][1]);
                *(__nv_bfloat162*)(g_qkv + (size_t)(r0 + 8) * LDC + col) =
                    __floats2bfloat162_rn(acc[ti][tj][2], acc[ti][tj][3]);
            } else {
                float ga0 = gamma[col], ga1 = gamma[col + 1];
                float bp0 = bproj[col], bp1 = bproj[col + 1];
                {
                    float flag = g_cnt[r0] > 0.5f ? 1.f : 0.f;
                    size_t o = (size_t)r0 * LDC + col;
                    outp[o]     = feats[o]     + ga0 * (acc[ti][tj][0] + bp0 * flag);
                    outp[o + 1] = feats[o + 1] + ga1 * (acc[ti][tj][1] + bp1 * flag);
                }
                {
                    float flag = g_cnt[r0 + 8] > 0.5f ? 1.f : 0.f;
                    size_t o = (size_t)(r0 + 8) * LDC + col;
                    outp[o]     = feats[o]     + ga0 * (acc[ti][tj][2] + bp0 * flag);
                    outp[o + 1] = feats[o + 1] + ga1 * (acc[ti][tj][3] + bp1 * flag);
                }
            }
        }
    }
}

// ---------------------------------------------------------------------------
// per-group attention + scatter. 1 CTA per group, 128 threads.
// Per-head outputs scatter from registers via packed bf16x2 atomics.
// ---------------------------------------------------------------------------
__global__ void __launch_bounds__(128) attn_k(const int* __restrict__ gidxw,
                                              const float* __restrict__ gmask) {
    extern __shared__ float sm[];
    float* qs  = sm;                  // 32*68
    float* ksm = qs  + 32 * 68;       // 32*68
    float* vsm = ksm + 32 * 68;       // 32*68
    float* pr  = vsm + 32 * 68;       // 32*36
    int*   Pp  = (int*)(pr + 32 * 36);   // 32
    float* mm  = (float*)(Pp + 32);      // 32

    const int tid = threadIdx.x;
    const int base = blockIdx.x * KG;
    const int bb = blockIdx.x >> 9;  // batch = group / 512

    if (tid < 32) {
        int slot = base + tid;
        int p = g_is64 ? gidxw[2 * slot] : gidxw[slot];
        p = p < 0 ? 0 : (p > 8191 ? 8191 : p);
        Pp[tid] = bb * 8192 + p;
        mm[tid] = gmask[slot];
    }
    __syncthreads();

    const int qi = tid >> 2, quar = tid & 3;
    const int grow = tid >> 2, gc0 = tid & 3;

    const int   myP = Pp[qi];
    const float myW = mm[qi];

    for (int h = 0; h < NH; h++) {
        const size_t rowbase = (size_t)Pp[grow] * QKVD + h * DHD;
#pragma unroll
        for (int sec = 0; sec < 3; sec++) {
            float* dst = (sec == 0) ? qs : (sec == 1) ? ksm : vsm;
            const __nv_bfloat16* src = g_qkv + rowbase + sec * CDIM;
#pragma unroll
            for (int half = 0; half < 2; half++) {
                int ch = gc0 + half * 4;
                uint4 u = *(const uint4*)(src + ch * 8);
                const __nv_bfloat162* pb = (const __nv_bfloat162*)&u;
                float* d = dst + grow * 68 + ch * 8;
#pragma unroll
                for (int j = 0; j < 4; j++) {
                    float2 f = __bfloat1622float2(pb[j]);
                    *(float2*)(d + 2 * j) = f;
                }
            }
        }
        __syncthreads();

        float s[8];
#pragma unroll
        for (int j = 0; j < 8; j++) s[j] = 0.f;
#pragma unroll
        for (int d4 = 0; d4 < 16; d4++) {
            float4 qv = *(const float4*)(qs + qi * 68 + d4 * 4);
#pragma unroll
            for (int j = 0; j < 8; j++) {
                float4 kv = *(const float4*)(ksm + (quar * 8 + j) * 68 + d4 * 4);
                s[j] += qv.x * kv.x + qv.y * kv.y + qv.z * kv.z + qv.w * kv.w;
            }
        }
        float mx = -3e38f;
#pragma unroll
        for (int j = 0; j < 8; j++) {
            s[j] = s[j] * 0.125f + (mm[quar * 8 + j] > 0.f ? 0.f : -1e9f);
            mx = fmaxf(mx, s[j]);
        }
        mx = fmaxf(mx, __shfl_xor_sync(0xffffffffu, mx, 1));
        mx = fmaxf(mx, __shfl_xor_sync(0xffffffffu, mx, 2));
        float ssum = 0.f;
#pragma unroll
        for (int j = 0; j < 8; j++) { s[j] = __expf(s[j] - mx); ssum += s[j]; }
        ssum += __shfl_xor_sync(0xffffffffu, ssum, 1);
        ssum += __shfl_xor_sync(0xffffffffu, ssum, 2);
        float rinv = 1.f / ssum;
#pragma unroll
        for (int j = 0; j < 8; j++) pr[qi * 36 + quar * 8 + j] = s[j] * rinv;
        __syncthreads();

        float4 o[4];
#pragma unroll
        for (int c = 0; c < 4; c++) o[c] = make_float4(0.f, 0.f, 0.f, 0.f);
        for (int kj = 0; kj < 32; kj++) {
            float a = pr[qi * 36 + kj];
#pragma unroll
            for (int c = 0; c < 4; c++) {
                float4 vv = *(const float4*)(vsm + kj * 68 + quar * 16 + c * 4);
                o[c].x += a * vv.x; o[c].y += a * vv.y;
                o[c].z += a * vv.z; o[c].w += a * vv.w;
            }
        }
        if (myW != 0.f) {
            __nv_bfloat162* dst = g_acc2 + (size_t)myP * (CDIM / 2) + h * (DHD / 2) + quar * 8;
#pragma unroll
            for (int c = 0; c < 4; c++) {
                atomicAdd(dst + c * 2 + 0, __floats2bfloat162_rn(o[c].x * myW, o[c].y * myW));
                atomicAdd(dst + c * 2 + 1, __floats2bfloat162_rn(o[c].z * myW, o[c].w * myW));
            }
        }
        __syncthreads();
    }

    if (tid < 32 && mm[tid] != 0.f) atomicAdd(g_cnt + Pp[tid], mm[tid]);
}

// ---------------------------------------------------------------------------
// launch — ONLY kernel launches (graph-capture safe)
// ---------------------------------------------------------------------------
extern "C" void kernel_launch(void* const* d_in, const int* in_sizes, int n_in,
                              void* d_out, int out_size) {
    const float* feats = (const float*)d_in[0];
    const int*   gidxw = (const int*)d_in[1];
    const float* gmask = (const float*)d_in[2];
    const float* wqkv  = (const float*)d_in[3];
    const float* wproj = (const float*)d_in[4];
    const float* bproj = (const float*)d_in[5];
    const float* gamma = (const float*)d_in[6];
    float*       outp  = (float*)d_out;

    const int gemm_smem = 2 * 2 * 128 * 40 * 2;              // 40960 B
    const int attn_smem = (32 * 68 * 3 + 32 * 36 + 64) * 4;  // 30976 B

    k_sniff<<<1, 32>>>(gidxw);

    const int nZero = NPTS * CDIM / 8 + NPTS / 4;
    k_zero<<<(nZero + 255) / 256, 256>>>();

    const int nFeat4 = NPTS * CDIM / 4;
    k_conv_feats<<<(nFeat4 + 255) / 256, 256>>>(feats);

    const int nW4 = QKVD * CDIM / 4 + CDIM * CDIM / 4;
    k_conv_w<<<(nW4 + 255) / 256, 256>>>(wqkv, wproj);

    gemm_k<false><<<dim3(QKVD / 128, NPTS / 128), 256, gemm_smem>>>(nullptr, nullptr, nullptr, nullptr);

    attn_k<<<NGRP, 128, attn_smem>>>(gidxw, gmask);

    const int nAvg = NPTS * CDIM / 8;
    k_avg<<<(nAvg + 255) / 256, 256>>>();

    gemm_k<true><<<dim3(CDIM / 128, NPTS / 128), 256, gemm_smem>>>(feats, gamma, bproj, outp);
}

// round 8
// speedup vs baseline: 2.6034x; 2.4888x over previous
#include <cuda_runtime.h>
#include <cuda_bf16.h>
#include <cstdint>

// ---------------------------------------------------------------------------
// GroupLocalAttention (sm_100 baseline ISA: mma.sync + ldmatrix + cp.async):
//   1) QKV_all[p,1152] = feats[p,:] @ Wqkv^T       (bf16 mma GEMM, per point)
//   2) per (group, head-triple): gather bf16 q/k/v, tensor-core attention,
//      register softmax with folded scatter weights, bf16x2 atomic scatter
//   3) avg = acc / max(cnt,1)  (bf16)
//   4) out = feats + gamma*(avg @ Wproj^T + b_proj*[cnt>0])  (bf16 mma GEMM)
// ---------------------------------------------------------------------------

#define NPTS 65536      // B * N_MAX
#define CDIM 384
#define QKVD 1152
#define NGRP 4096       // B * G
#define KG   32
#define NH   6
#define DHD  64

__device__ __align__(16) __nv_bfloat16  g_feats_bf[(size_t)NPTS * CDIM];
__device__ __align__(16) __nv_bfloat16  g_qkv[(size_t)NPTS * QKVD];
__device__ __align__(16) __nv_bfloat162 g_acc2[(size_t)NPTS * CDIM / 2];
__device__ __align__(16) float          g_cnt[NPTS];
__device__ __align__(16) __nv_bfloat16  g_avg_bf[(size_t)NPTS * CDIM];
__device__ __align__(16) __nv_bfloat16  g_wqkv_bf[QKVD * CDIM];
__device__ __align__(16) __nv_bfloat16  g_wproj_bf[CDIM * CDIM];
__device__ int g_is64;

// ---------------------------------------------------------------------------
// helpers
// ---------------------------------------------------------------------------
__device__ __forceinline__ void ldsm4(unsigned& x, unsigned& y, unsigned& z, unsigned& w,
                                      const void* p) {
    unsigned a = (unsigned)__cvta_generic_to_shared(p);
    asm volatile("ldmatrix.sync.aligned.m8n8.x4.shared.b16 {%0,%1,%2,%3}, [%4];"
                 : "=r"(x), "=r"(y), "=r"(z), "=r"(w) : "r"(a));
}
__device__ __forceinline__ void ldsm4t(unsigned& x, unsigned& y, unsigned& z, unsigned& w,
                                       const void* p) {
    unsigned a = (unsigned)__cvta_generic_to_shared(p);
    asm volatile("ldmatrix.sync.aligned.m8n8.x4.trans.shared.b16 {%0,%1,%2,%3}, [%4];"
                 : "=r"(x), "=r"(y), "=r"(z), "=r"(w) : "r"(a));
}
__device__ __forceinline__ void mma16816(float* c, const unsigned* a,
                                         unsigned b0, unsigned b1) {
    asm volatile(
        "mma.sync.aligned.m16n8k16.row.col.f32.bf16.bf16.f32 "
        "{%0,%1,%2,%3},{%4,%5,%6,%7},{%8,%9},{%0,%1,%2,%3};\n"
        : "+f"(c[0]), "+f"(c[1]), "+f"(c[2]), "+f"(c[3])
        : "r"(a[0]), "r"(a[1]), "r"(a[2]), "r"(a[3]), "r"(b0), "r"(b1));
}
__device__ __forceinline__ void cp16(unsigned dst, const void* src) {
    asm volatile("cp.async.cg.shared.global [%0], [%1], 16;\n" :: "r"(dst), "l"(src));
}
__device__ __forceinline__ __nv_bfloat162 pack2(float a, float b) {
    return __floats2bfloat162_rn(a, b);
}

// ---------------------------------------------------------------------------
// prep kernels
// ---------------------------------------------------------------------------
__global__ void k_sniff(const int* __restrict__ w) {
    if (threadIdx.x == 0 && blockIdx.x == 0) {
        int all0 = 1;
        for (int i = 1; i < 64; i += 2) all0 &= (w[i] == 0 || w[i] == -1);
        g_is64 = all0;
    }
}

__global__ void k_zero() {
    int i = blockIdx.x * blockDim.x + threadIdx.x;
    const int nAccV = NPTS * CDIM / 8;
    const int nCntV = NPTS / 4;
    if (i < nAccV) {
        ((float4*)g_acc2)[i] = make_float4(0.f, 0.f, 0.f, 0.f);
    } else if (i < nAccV + nCntV) {
        ((float4*)g_cnt)[i - nAccV] = make_float4(0.f, 0.f, 0.f, 0.f);
    }
}

__global__ void k_conv_feats(const float* __restrict__ src) {
    int i = blockIdx.x * blockDim.x + threadIdx.x;
    const int n4 = NPTS * CDIM / 4;
    if (i < n4) {
        float4 v = ((const float4*)src)[i];
        ((__nv_bfloat162*)g_feats_bf)[2 * i]     = __floats2bfloat162_rn(v.x, v.y);
        ((__nv_bfloat162*)g_feats_bf)[2 * i + 1] = __floats2bfloat162_rn(v.z, v.w);
    }
}

__global__ void k_conv_w(const float* __restrict__ wqkv, const float* __restrict__ wproj) {
    int i = blockIdx.x * blockDim.x + threadIdx.x;
    const int n1 = QKVD * CDIM / 4;
    const int n2 = CDIM * CDIM / 4;
    if (i < n1) {
        float4 v = ((const float4*)wqkv)[i];
        ((__nv_bfloat162*)g_wqkv_bf)[2 * i]     = __floats2bfloat162_rn(v.x, v.y);
        ((__nv_bfloat162*)g_wqkv_bf)[2 * i + 1] = __floats2bfloat162_rn(v.z, v.w);
    } else if (i < n1 + n2) {
        int j = i - n1;
        float4 v = ((const float4*)wproj)[j];
        ((__nv_bfloat162*)g_wproj_bf)[2 * j]     = __floats2bfloat162_rn(v.x, v.y);
        ((__nv_bfloat162*)g_wproj_bf)[2 * j + 1] = __floats2bfloat162_rn(v.z, v.w);
    }
}

__global__ void k_avg() {
    int i = blockIdx.x * blockDim.x + threadIdx.x;  // uint4 = 8 bf16
    const int n = NPTS * CDIM / 8;
    if (i < n) {
        int row = (i * 8) / CDIM;
        float sc = 1.f / fmaxf(g_cnt[row], 1.f);
        uint4 u = ((const uint4*)g_acc2)[i];
        uint32_t w[4] = {u.x, u.y, u.z, u.w};
#pragma unroll
        for (int j = 0; j < 4; j++) {
            float2 f = __bfloat1622float2(*(__nv_bfloat162*)&w[j]);
            __nv_bfloat162 h = __floats2bfloat162_rn(f.x * sc, f.y * sc);
            w[j] = *(uint32_t*)&h;
        }
        ((uint4*)g_avg_bf)[i] = make_uint4(w[0], w[1], w[2], w[3]);
    }
}

// ---------------------------------------------------------------------------
// bf16 GEMM: 128x128 CTA tile, K-tile 32, cp.async double buffer,
// ldmatrix.x4 fragment loads + mma.sync m16n8k16.  smem 40960 B.
// ---------------------------------------------------------------------------
template <bool EPI>
__global__ void __launch_bounds__(256) gemm_k(const float* __restrict__ feats,
                                              const float* __restrict__ gamma,
                                              const float* __restrict__ bproj,
                                              float* __restrict__ outp) {
    const __nv_bfloat16* __restrict__ A  = EPI ? g_avg_bf : g_feats_bf;
    const __nv_bfloat16* __restrict__ Bw = EPI ? g_wproj_bf : g_wqkv_bf;
    constexpr int LDC = EPI ? CDIM : QKVD;

    extern __shared__ __nv_bfloat16 smemg[];
    constexpr int LDS_ = 40;
    constexpr int TSZ = 128 * LDS_;

    const int m0 = blockIdx.y * 128;
    const int n0 = blockIdx.x * 128;
    const int tid = threadIdx.x;
    const int warp = tid >> 5, lane = tid & 31;
    const int wm = warp & 3, wn = warp >> 2;
    const int g = lane >> 2, q = lane & 3;
    const int lr  = tid >> 1;
    const int lc0 = (tid & 1) * 2;
    const int lm_r = lane & 15;
    const int lm_c = (lane >> 4) * 8;

    auto load_stage = [&](int kt, int stage) {
        __nv_bfloat16* sA = smemg + stage * 2 * TSZ;
        __nv_bfloat16* sB = sA + TSZ;
        const void* gA = A  + (size_t)(m0 + lr) * CDIM + kt * 32;
        const void* gB = Bw + (size_t)(n0 + lr) * CDIM + kt * 32;
        unsigned dA = (unsigned)__cvta_generic_to_shared(sA + lr * LDS_);
        unsigned dB = (unsigned)__cvta_generic_to_shared(sB + lr * LDS_);
#pragma unroll
        for (int i = 0; i < 2; i++) {
            int ch = lc0 + i;
            cp16(dA + ch * 16, (const char*)gA + ch * 16);
            cp16(dB + ch * 16, (const char*)gB + ch * 16);
        }
    };

    float acc[2][8][4];
#pragma unroll
    for (int ti = 0; ti < 2; ti++)
#pragma unroll
        for (int tj = 0; tj < 8; tj++)
#pragma unroll
            for (int r = 0; r < 4; r++) acc[ti][tj][r] = 0.f;

    load_stage(0, 0);
    asm volatile("cp.async.commit_group;\n");

    constexpr int KT = CDIM / 32;
    for (int kt = 0; kt < KT; kt++) {
        if (kt + 1 < KT) {
            load_stage(kt + 1, (kt + 1) & 1);
            asm volatile("cp.async.commit_group;\n");
            asm volatile("cp.async.wait_group 1;\n");
        } else {
            asm volatile("cp.async.wait_group 0;\n");
        }
        __syncthreads();
        const __nv_bfloat16* sA = smemg + (kt & 1) * 2 * TSZ;
        const __nv_bfloat16* sB = sA + TSZ;
#pragma unroll
        for (int ks = 0; ks < 2; ks++) {
            const int k0 = ks * 16;
            unsigned af[2][4];
#pragma unroll
            for (int ti = 0; ti < 2; ti++) {
                int R = wm * 32 + ti * 16;
                ldsm4(af[ti][0], af[ti][1], af[ti][2], af[ti][3],
                      sA + (R + lm_r) * LDS_ + k0 + lm_c);
            }
            unsigned bfr[8][2];
#pragma unroll
            for (int pr2 = 0; pr2 < 4; pr2++) {
                int Cn0 = wn * 64 + pr2 * 16;
                unsigned x, y, z, w;
                ldsm4(x, y, z, w, sB + (Cn0 + lm_r) * LDS_ + k0 + lm_c);
                bfr[2 * pr2][0]     = x;
                bfr[2 * pr2][1]     = z;
                bfr[2 * pr2 + 1][0] = y;
                bfr[2 * pr2 + 1][1] = w;
            }
#pragma unroll
            for (int ti = 0; ti < 2; ti++)
#pragma unroll
                for (int tj = 0; tj < 8; tj++)
                    mma16816(acc[ti][tj], af[ti], bfr[tj][0], bfr[tj][1]);
        }
        __syncthreads();
    }

#pragma unroll
    for (int ti = 0; ti < 2; ti++) {
        int r0 = m0 + wm * 32 + ti * 16 + g;
#pragma unroll
        for (int tj = 0; tj < 8; tj++) {
            int col = n0 + wn * 64 + tj * 8 + 2 * q;
            if (!EPI) {
                *(__nv_bfloat162*)(g_qkv + (size_t)r0 * LDC + col) =
                    __floats2bfloat162_rn(acc[ti][tj][0], acc[ti][tj][1]);
                *(__nv_bfloat162*)(g_qkv + (size_t)(r0 + 8) * LDC + col) =
                    __floats2bfloat162_rn(acc[ti][tj][2], acc[ti][tj][3]);
            } else {
                float ga0 = gamma[col], ga1 = gamma[col + 1];
                float bp0 = bproj[col], bp1 = bproj[col + 1];
                {
                    float flag = g_cnt[r0] > 0.5f ? 1.f : 0.f;
                    size_t o = (size_t)r0 * LDC + col;
                    outp[o]     = feats[o]     + ga0 * (acc[ti][tj][0] + bp0 * flag);
                    outp[o + 1] = feats[o + 1] + ga1 * (acc[ti][tj][1] + bp1 * flag);
                }
                {
                    float flag = g_cnt[r0 + 8] > 0.5f ? 1.f : 0.f;
                    size_t o = (size_t)(r0 + 8) * LDC + col;
                    outp[o]     = feats[o]     + ga0 * (acc[ti][tj][2] + bp0 * flag);
                    outp[o + 1] = feats[o + 1] + ga1 * (acc[ti][tj][3] + bp1 * flag);
                }
            }
        }
    }
}

// ---------------------------------------------------------------------------
// tensor-core attention. 1 CTA per (group, head-triple): 8192 CTAs x 96 thr.
// Warp w handles head h0+w. All-bf16 smem (cp.async gather), mma scores,
// register softmax (scatter weight folded into P), mma P*V, bf16x2 atomics.
// smem: 9 segs x 32 rows x 72 bf16 (144B padded rows) + idx/mask = ~41.7KB
// ---------------------------------------------------------------------------
#define ASEG 72

__global__ void __launch_bounds__(96) attn_k(const int* __restrict__ gidxw,
                                             const float* __restrict__ gmask) {
    extern __shared__ __align__(16) __nv_bfloat16 segs[];  // 9*2304
    int*   Pp = (int*)(segs + 9 * 2304);
    float* mm = (float*)(Pp + 32);

    const int tid  = threadIdx.x;
    const int lane = tid & 31;
    const int warp = tid >> 5;          // 0..2
    const int grp  = blockIdx.x >> 1;
    const int trip = blockIdx.x & 1;
    const int h0   = trip * 3;
    const int bb   = grp >> 9;          // batch

    if (tid < 32) {
        int slot = grp * KG + tid;
        int p = g_is64 ? gidxw[2 * slot] : gidxw[slot];
        p = p < 0 ? 0 : (p > 8191 ? 8191 : p);
        Pp[tid] = bb * 8192 + p;
        mm[tid] = gmask[slot];
    }
    __syncthreads();

    // gather: 9 segments (3 heads x q/k/v), 32 rows x 128B each
    const unsigned sbase = (unsigned)__cvta_generic_to_shared(segs);
    for (int i = tid; i < 9 * 256; i += 96) {
        int s = i >> 8;              // seg 0..8
        int r = (i >> 3) & 31;       // row
        int c = i & 7;               // 16B chunk
        int hh = s / 3, sec = s - 3 * hh;
        const __nv_bfloat16* src =
            g_qkv + (size_t)Pp[r] * QKVD + sec * CDIM + (h0 + hh) * DHD + c * 8;
        cp16(sbase + (unsigned)((s * 2304 + r * ASEG + c * 8) * 2), src);
    }
    asm volatile("cp.async.commit_group;\n");
    asm volatile("cp.async.wait_group 0;\n");
    __syncthreads();

    const __nv_bfloat16* Qs = segs + (warp * 3 + 0) * 2304;
    const __nv_bfloat16* Ks = segs + (warp * 3 + 1) * 2304;
    const __nv_bfloat16* Vs = segs + (warp * 3 + 2) * 2304;
    const int head = h0 + warp;

    const int g = lane >> 2, q = lane & 3;
    const int lm_r = lane & 15;
    const int lm_c = (lane >> 4) * 8;

    // ---- scores S = Q @ K^T ----
    float sacc[2][4][4];
#pragma unroll
    for (int mi = 0; mi < 2; mi++)
#pragma unroll
        for (int nj = 0; nj < 4; nj++)
#pragma unroll
            for (int r = 0; r < 4; r++) sacc[mi][nj][r] = 0.f;

#pragma unroll
    for (int kd = 0; kd < 4; kd++) {
        unsigned aq[2][4];
#pragma unroll
        for (int mi = 0; mi < 2; mi++)
            ldsm4(aq[mi][0], aq[mi][1], aq[mi][2], aq[mi][3],
                  Qs + (mi * 16 + lm_r) * ASEG + kd * 16 + lm_c);
        unsigned bfr[4][2];
#pragma unroll
        for (int ng = 0; ng < 2; ng++) {
            unsigned x, y, z, w;
            ldsm4(x, y, z, w, Ks + (ng * 16 + lm_r) * ASEG + kd * 16 + lm_c);
            bfr[2 * ng][0]     = x;
            bfr[2 * ng][1]     = z;
            bfr[2 * ng + 1][0] = y;
            bfr[2 * ng + 1][1] = w;
        }
#pragma unroll
        for (int mi = 0; mi < 2; mi++)
#pragma unroll
            for (int nj = 0; nj < 4; nj++)
                mma16816(sacc[mi][nj], aq[mi], bfr[nj][0], bfr[nj][1]);
    }

    // ---- masked softmax (rows g / g+8 per m-tile), fold weight & 1/sum ----
    float bias0[4], bias1[4];
#pragma unroll
    for (int nj = 0; nj < 4; nj++) {
        bias0[nj] = mm[nj * 8 + 2 * q]     > 0.f ? 0.f : -1e9f;
        bias1[nj] = mm[nj * 8 + 2 * q + 1] > 0.f ? 0.f : -1e9f;
    }
    unsigned pa[2][2][4];   // [mi][ks][4]  bf16x2 A-fragments of P
    float wr0[2], wr1[2];
    int   P0[2], P1[2];
#pragma unroll
    for (int mi = 0; mi < 2; mi++) {
        wr0[mi] = mm[mi * 16 + g];
        wr1[mi] = mm[mi * 16 + g + 8];
        P0[mi]  = Pp[mi * 16 + g];
        P1[mi]  = Pp[mi * 16 + g + 8];

        float m0 = -3e38f, m1 = -3e38f;
#pragma unroll
        for (int nj = 0; nj < 4; nj++) {
            sacc[mi][nj][0] = sacc[mi][nj][0] * 0.125f + bias0[nj];
            sacc[mi][nj][1] = sacc[mi][nj][1] * 0.125f + bias1[nj];
            sacc[mi][nj][2] = sacc[mi][nj][2] * 0.125f + bias0[nj];
            sacc[mi][nj][3] = sacc[mi][nj][3] * 0.125f + bias1[nj];
            m0 = fmaxf(m0, fmaxf(sacc[mi][nj][0], sacc[mi][nj][1]));
            m1 = fmaxf(m1, fmaxf(sacc[mi][nj][2], sacc[mi][nj][3]));
        }
        m0 = fmaxf(m0, __shfl_xor_sync(0xffffffffu, m0, 1));
        m0 = fmaxf(m0, __shfl_xor_sync(0xffffffffu, m0, 2));
        m1 = fmaxf(m1, __shfl_xor_sync(0xffffffffu, m1, 1));
        m1 = fmaxf(m1, __shfl_xor_sync(0xffffffffu, m1, 2));

        float s0 = 0.f, s1 = 0.f;
#pragma unroll
        for (int nj = 0; nj < 4; nj++) {
            sacc[mi][nj][0] = __expf(sacc[mi][nj][0] - m0);
            sacc[mi][nj][1] = __expf(sacc[mi][nj][1] - m0);
            sacc[mi][nj][2] = __expf(sacc[mi][nj][2] - m1);
            sacc[mi][nj][3] = __expf(sacc[mi][nj][3] - m1);
            s0 += sacc[mi][nj][0] + sacc[mi][nj][1];
            s1 += sacc[mi][nj][2] + sacc[mi][nj][3];
        }
        s0 += __shfl_xor_sync(0xffffffffu, s0, 1);
        s0 += __shfl_xor_sync(0xffffffffu, s0, 2);
        s1 += __shfl_xor_sync(0xffffffffu, s1, 1);
        s1 += __shfl_xor_sync(0xffffffffu, s1, 2);
        float r0 = wr0[mi] / s0;       // scatter weight folded into P
        float r1 = wr1[mi] / s1;

#pragma unroll
        for (int ks = 0; ks < 2; ks++) {
            __nv_bfloat162 h0p = pack2(sacc[mi][2 * ks][0] * r0, sacc[mi][2 * ks][1] * r0);
            __nv_bfloat162 h1p = pack2(sacc[mi][2 * ks][2] * r1, sacc[mi][2 * ks][3] * r1);
            __nv_bfloat162 h2p = pack2(sacc[mi][2 * ks + 1][0] * r0, sacc[mi][2 * ks + 1][1] * r0);
            __nv_bfloat162 h3p = pack2(sacc[mi][2 * ks + 1][2] * r1, sacc[mi][2 * ks + 1][3] * r1);
            pa[mi][ks][0] = *(unsigned*)&h0p;
            pa[mi][ks][1] = *(unsigned*)&h1p;
            pa[mi][ks][2] = *(unsigned*)&h2p;
            pa[mi][ks][3] = *(unsigned*)&h3p;
        }
    }

    // ---- O = P @ V  (V loaded transposed via ldmatrix.trans) ----
    float oacc[2][8][4];
#pragma unroll
    for (int mi = 0; mi < 2; mi++)
#pragma unroll
        for (int dn = 0; dn < 8; dn++)
#pragma unroll
            for (int r = 0; r < 4; r++) oacc[mi][dn][r] = 0.f;

#pragma unroll
    for (int ks = 0; ks < 2; ks++) {
#pragma unroll
        for (int dg = 0; dg < 4; dg++) {
            unsigned x, y, z, w;
            ldsm4t(x, y, z, w, Vs + (ks * 16 + lm_r) * ASEG + dg * 16 + lm_c);
#pragma unroll
            for (int mi = 0; mi < 2; mi++) {
                mma16816(oacc[mi][2 * dg],     pa[mi][ks], x, y);
                mma16816(oacc[mi][2 * dg + 1], pa[mi][ks], z, w);
            }
        }
    }

    // ---- scatter (weights already folded into P) ----
#pragma unroll
    for (int mi = 0; mi < 2; mi++) {
        __nv_bfloat162* d0 = g_acc2 + (size_t)P0[mi] * (CDIM / 2) + head * 32 + q;
        __nv_bfloat162* d1 = g_acc2 + (size_t)P1[mi] * (CDIM / 2) + head * 32 + q;
        const bool w0 = (wr0[mi] != 0.f);
        const bool w1 = (wr1[mi] != 0.f);
#pragma unroll
        for (int dn = 0; dn < 8; dn++) {
            if (w0) {
                __nv_bfloat162 v = pack2(oacc[mi][dn][0], oacc[mi][dn][1]);
                atomicAdd(d0 + dn * 4, v);
            }
            if (w1) {
                __nv_bfloat162 v = pack2(oacc[mi][dn][2], oacc[mi][dn][3]);
                atomicAdd(d1 + dn * 4, v);
            }
        }
    }

    if (trip == 0 && tid < 32 && mm[tid] != 0.f) atomicAdd(g_cnt + Pp[tid], mm[tid]);
}

// ---------------------------------------------------------------------------
// launch — ONLY kernel launches (graph-capture safe)
// ---------------------------------------------------------------------------
extern "C" void kernel_launch(void* const* d_in, const int* in_sizes, int n_in,
                              void* d_out, int out_size) {
    const float* feats = (const float*)d_in[0];
    const int*   gidxw = (const int*)d_in[1];
    const float* gmask = (const float*)d_in[2];
    const float* wqkv  = (const float*)d_in[3];
    const float* wproj = (const float*)d_in[4];
    const float* bproj = (const float*)d_in[5];
    const float* gamma = (const float*)d_in[6];
    float*       outp  = (float*)d_out;

    const int gemm_smem = 2 * 2 * 128 * 40 * 2;            // 40960 B
    const int attn_smem = 9 * 2304 * 2 + 32 * 4 + 32 * 4;  // 41728 B

    k_sniff<<<1, 32>>>(gidxw);

    const int nZero = NPTS * CDIM / 8 + NPTS / 4;
    k_zero<<<(nZero + 255) / 256, 256>>>();

    const int nFeat4 = NPTS * CDIM / 4;
    k_conv_feats<<<(nFeat4 + 255) / 256, 256>>>(feats);

    const int nW4 = QKVD * CDIM / 4 + CDIM * CDIM / 4;
    k_conv_w<<<(nW4 + 255) / 256, 256>>>(wqkv, wproj);

    gemm_k<false><<<dim3(QKVD / 128, NPTS / 128), 256, gemm_smem>>>(nullptr, nullptr, nullptr, nullptr);

    attn_k<<<NGRP * 2, 96, attn_smem>>>(gidxw, gmask);

    const int nAvg = NPTS * CDIM / 8;
    k_avg<<<(nAvg + 255) / 256, 256>>>();

    gemm_k<true><<<dim3(CDIM / 128, NPTS / 128), 256, gemm_smem>>>(feats, gamma, bproj, outp);
}

// round 9
// speedup vs baseline: 2.7211x; 1.0452x over previous
#include <cuda_runtime.h>
#include <cuda_bf16.h>
#include <cstdint>

// ---------------------------------------------------------------------------
// GroupLocalAttention (sm_100 baseline ISA: mma.sync + ldmatrix + cp.async):
//   0) k_prep: zero acc/cnt, convert weights to bf16, sniff idx dtype
//   1) QKV_all[p,1152] = feats[p,:] @ Wqkv^T   (gemm1: A read f32->bf16 inline)
//   2) per (group, head-triple): tensor-core attention, bf16x2 atomic scatter
//   3) out = feats + gamma*((acc/cnt) @ Wproj^T + b_proj*[cnt>0])
//      (gemm2: 1/cnt folded into epilogue — diag scaling commutes with GEMM)
// ---------------------------------------------------------------------------

#define NPTS 65536      // B * N_MAX
#define CDIM 384
#define QKVD 1152
#define NGRP 4096       // B * G
#define KG   32
#define NH   6
#define DHD  64

__device__ __align__(16) __nv_bfloat16  g_qkv[(size_t)NPTS * QKVD];
__device__ __align__(16) __nv_bfloat162 g_acc2[(size_t)NPTS * CDIM / 2];
__device__ __align__(16) float          g_cnt[NPTS];
__device__ __align__(16) __nv_bfloat16  g_wqkv_bf[QKVD * CDIM];
__device__ __align__(16) __nv_bfloat16  g_wproj_bf[CDIM * CDIM];
__device__ int g_is64;

// ---------------------------------------------------------------------------
// helpers
// ---------------------------------------------------------------------------
__device__ __forceinline__ void ldsm4(unsigned& x, unsigned& y, unsigned& z, unsigned& w,
                                      const void* p) {
    unsigned a = (unsigned)__cvta_generic_to_shared(p);
    asm volatile("ldmatrix.sync.aligned.m8n8.x4.shared.b16 {%0,%1,%2,%3}, [%4];"
                 : "=r"(x), "=r"(y), "=r"(z), "=r"(w) : "r"(a));
}
__device__ __forceinline__ void ldsm4t(unsigned& x, unsigned& y, unsigned& z, unsigned& w,
                                       const void* p) {
    unsigned a = (unsigned)__cvta_generic_to_shared(p);
    asm volatile("ldmatrix.sync.aligned.m8n8.x4.trans.shared.b16 {%0,%1,%2,%3}, [%4];"
                 : "=r"(x), "=r"(y), "=r"(z), "=r"(w) : "r"(a));
}
__device__ __forceinline__ void mma16816(float* c, const unsigned* a,
                                         unsigned b0, unsigned b1) {
    asm volatile(
        "mma.sync.aligned.m16n8k16.row.col.f32.bf16.bf16.f32 "
        "{%0,%1,%2,%3},{%4,%5,%6,%7},{%8,%9},{%0,%1,%2,%3};\n"
        : "+f"(c[0]), "+f"(c[1]), "+f"(c[2]), "+f"(c[3])
        : "r"(a[0]), "r"(a[1]), "r"(a[2]), "r"(a[3]), "r"(b0), "r"(b1));
}
__device__ __forceinline__ void cp16(unsigned dst, const void* src) {
    asm volatile("cp.async.cg.shared.global [%0], [%1], 16;\n" :: "r"(dst), "l"(src));
}
__device__ __forceinline__ __nv_bfloat162 pack2(float a, float b) {
    return __floats2bfloat162_rn(a, b);
}

// ---------------------------------------------------------------------------
// fused prep: zero acc2+cnt, convert both weight matrices, sniff idx dtype
// ---------------------------------------------------------------------------
__global__ void k_prep(const int* __restrict__ w,
                       const float* __restrict__ wqkv,
                       const float* __restrict__ wproj) {
    const int nAccV = NPTS * CDIM / 8;   // float4 units over bf16 acc
    const int nCntV = NPTS / 4;
    const int n1 = QKVD * CDIM / 4;
    const int n2 = CDIM * CDIM / 4;
    int i = blockIdx.x * blockDim.x + threadIdx.x;
    if (i < nAccV) {
        ((float4*)g_acc2)[i] = make_float4(0.f, 0.f, 0.f, 0.f);
    } else if (i < nAccV + nCntV) {
        ((float4*)g_cnt)[i - nAccV] = make_float4(0.f, 0.f, 0.f, 0.f);
    } else {
        int j = i - nAccV - nCntV;
        if (j < n1) {
            float4 v = ((const float4*)wqkv)[j];
            ((__nv_bfloat162*)g_wqkv_bf)[2 * j]     = __floats2bfloat162_rn(v.x, v.y);
            ((__nv_bfloat162*)g_wqkv_bf)[2 * j + 1] = __floats2bfloat162_rn(v.z, v.w);
        } else if (j < n1 + n2) {
            int k = j - n1;
            float4 v = ((const float4*)wproj)[k];
            ((__nv_bfloat162*)g_wproj_bf)[2 * k]     = __floats2bfloat162_rn(v.x, v.y);
            ((__nv_bfloat162*)g_wproj_bf)[2 * k + 1] = __floats2bfloat162_rn(v.z, v.w);
        } else if (j == n1 + n2) {
            int all0 = 1;
            for (int t = 1; t < 64; t += 2) all0 &= (w[t] == 0 || w[t] == -1);
            g_is64 = all0;
        }
    }
}

// ---------------------------------------------------------------------------
// bf16 GEMM: 128x128 CTA tile, K-tile 32, mma.sync m16n8k16 + ldmatrix.
// EPI=false (gemm1): A = feats f32, converted inline (LDG->cvt->STS with
//   register prefetch, distance 2); B = g_wqkv_bf via cp.async. C -> g_qkv.
// EPI=true  (gemm2): A = g_acc2 (raw bf16 sums), B = g_wproj_bf, both
//   cp.async; epilogue applies 1/max(cnt,1), gamma, bias, feats add.
// smem 40960 B.
// ---------------------------------------------------------------------------
template <bool EPI>
__global__ void __launch_bounds__(256) gemm_k(const float* __restrict__ feats,
                                              const float* __restrict__ gamma,
                                              const float* __restrict__ bproj,
                                              float* __restrict__ outp) {
    const __nv_bfloat16* __restrict__ Bw = EPI ? g_wproj_bf : g_wqkv_bf;
    constexpr int LDC = EPI ? CDIM : QKVD;

    extern __shared__ __nv_bfloat16 smemg[];
    constexpr int LDS_ = 40;
    constexpr int TSZ = 128 * LDS_;

    const int m0 = blockIdx.y * 128;
    const int n0 = blockIdx.x * 128;
    const int tid = threadIdx.x;
    const int warp = tid >> 5, lane = tid & 31;
    const int wm = warp & 3, wn = warp >> 2;
    const int g = lane >> 2, q = lane & 3;
    const int lr  = tid >> 1;        // load row 0..127
    const int lc0 = (tid & 1) * 2;   // 16B-chunk base within 64B row
    const int lm_r = lane & 15;
    const int lm_c = (lane >> 4) * 8;

    // B loader (cp.async, both variants)
    auto load_B = [&](int kt, int stage) {
        __nv_bfloat16* sB = smemg + stage * 2 * TSZ + TSZ;
        const void* gB = Bw + (size_t)(n0 + lr) * CDIM + kt * 32;
        unsigned dB = (unsigned)__cvta_generic_to_shared(sB + lr * LDS_);
#pragma unroll
        for (int i = 0; i < 2; i++) {
            int ch = lc0 + i;
            cp16(dB + ch * 16, (const char*)gB + ch * 16);
        }
    };
    // A loader for EPI=true (cp.async from g_acc2 viewed as bf16 rows)
    auto load_A_cp = [&](int kt, int stage) {
        const __nv_bfloat16* A = (const __nv_bfloat16*)g_acc2;
        __nv_bfloat16* sA = smemg + stage * 2 * TSZ;
        const void* gA = A + (size_t)(m0 + lr) * CDIM + kt * 32;
        unsigned dA = (unsigned)__cvta_generic_to_shared(sA + lr * LDS_);
#pragma unroll
        for (int i = 0; i < 2; i++) {
            int ch = lc0 + i;
            cp16(dA + ch * 16, (const char*)gA + ch * 16);
        }
    };
    // A path for EPI=false: f32 LDG -> regs, later cvt+STS
    float4 rA[4];
    auto ldg_A = [&](int kt) {
        const float4* src = (const float4*)(feats + (size_t)(m0 + lr) * CDIM +
                                            kt * 32 + (tid & 1) * 16);
#pragma unroll
        for (int i = 0; i < 4; i++) rA[i] = src[i];
    };
    auto sts_A = [&](int stage) {
        __nv_bfloat16* sA = smemg + stage * 2 * TSZ;
        uint4* d = (uint4*)(sA + lr * LDS_ + (tid & 1) * 16);
        const float* f = (const float*)rA;
        uint4 o0, o1;
        __nv_bfloat162 h;
        h = pack2(f[0],  f[1]);  o0.x = *(unsigned*)&h;
        h = pack2(f[2],  f[3]);  o0.y = *(unsigned*)&h;
        h = pack2(f[4],  f[5]);  o0.z = *(unsigned*)&h;
        h = pack2(f[6],  f[7]);  o0.w = *(unsigned*)&h;
        h = pack2(f[8],  f[9]);  o1.x = *(unsigned*)&h;
        h = pack2(f[10], f[11]); o1.y = *(unsigned*)&h;
        h = pack2(f[12], f[13]); o1.z = *(unsigned*)&h;
        h = pack2(f[14], f[15]); o1.w = *(unsigned*)&h;
        d[0] = o0; d[1] = o1;
    };

    float acc[2][8][4];
#pragma unroll
    for (int ti = 0; ti < 2; ti++)
#pragma unroll
        for (int tj = 0; tj < 8; tj++)
#pragma unroll
            for (int r = 0; r < 4; r++) acc[ti][tj][r] = 0.f;

    constexpr int KT = CDIM / 32;   // 12

    // prologue: stages 0 and 1
    if constexpr (EPI) {
        load_A_cp(0, 0); load_B(0, 0);
        asm volatile("cp.async.commit_group;\n");
        load_A_cp(1, 1); load_B(1, 1);
        asm volatile("cp.async.commit_group;\n");
    } else {
        ldg_A(0); sts_A(0); load_B(0, 0);
        asm volatile("cp.async.commit_group;\n");
        ldg_A(1); sts_A(1); load_B(1, 1);
        asm volatile("cp.async.commit_group;\n");
    }

    for (int kt = 0; kt < KT; kt++) {
        const int s = kt & 1;
        if constexpr (!EPI) {
            if (kt + 2 < KT) ldg_A(kt + 2);   // overlap LDG latency with mma
        }
        if (kt + 1 < KT) asm volatile("cp.async.wait_group 1;\n");
        else             asm volatile("cp.async.wait_group 0;\n");
        __syncthreads();

        const __nv_bfloat16* sA = smemg + s * 2 * TSZ;
        const __nv_bfloat16* sB = sA + TSZ;
#pragma unroll
        for (int ks = 0; ks < 2; ks++) {
            const int k0 = ks * 16;
            unsigned af[2][4];
#pragma unroll
            for (int ti = 0; ti < 2; ti++) {
                int R = wm * 32 + ti * 16;
                ldsm4(af[ti][0], af[ti][1], af[ti][2], af[ti][3],
                      sA + (R + lm_r) * LDS_ + k0 + lm_c);
            }
            unsigned bfr[8][2];
#pragma unroll
            for (int pr2 = 0; pr2 < 4; pr2++) {
                int Cn0 = wn * 64 + pr2 * 16;
                unsigned x, y, z, w;
                ldsm4(x, y, z, w, sB + (Cn0 + lm_r) * LDS_ + k0 + lm_c);
                bfr[2 * pr2][0]     = x;
                bfr[2 * pr2][1]     = z;
                bfr[2 * pr2 + 1][0] = y;
                bfr[2 * pr2 + 1][1] = w;
            }
#pragma unroll
            for (int ti = 0; ti < 2; ti++)
#pragma unroll
                for (int tj = 0; tj < 8; tj++)
                    mma16816(acc[ti][tj], af[ti], bfr[tj][0], bfr[tj][1]);
        }
        __syncthreads();

        if (kt + 2 < KT) {
            if constexpr (EPI) {
                load_A_cp(kt + 2, s); load_B(kt + 2, s);
                asm volatile("cp.async.commit_group;\n");
            } else {
                sts_A(s); load_B(kt + 2, s);
                asm volatile("cp.async.commit_group;\n");
            }
        }
    }

    // epilogue
#pragma unroll
    for (int ti = 0; ti < 2; ti++) {
        int r0 = m0 + wm * 32 + ti * 16 + g;
        float inv0 = 0.f, inv1 = 0.f, fl0 = 0.f, fl1 = 0.f;
        if (EPI) {
            float c0 = g_cnt[r0], c1 = g_cnt[r0 + 8];
            inv0 = 1.f / fmaxf(c0, 1.f);
            inv1 = 1.f / fmaxf(c1, 1.f);
            fl0 = c0 > 0.5f ? 1.f : 0.f;
            fl1 = c1 > 0.5f ? 1.f : 0.f;
        }
#pragma unroll
        for (int tj = 0; tj < 8; tj++) {
            int col = n0 + wn * 64 + tj * 8 + 2 * q;
            if (!EPI) {
                *(__nv_bfloat162*)(g_qkv + (size_t)r0 * LDC + col) =
                    __floats2bfloat162_rn(acc[ti][tj][0], acc[ti][tj][1]);
                *(__nv_bfloat162*)(g_qkv + (size_t)(r0 + 8) * LDC + col) =
                    __floats2bfloat162_rn(acc[ti][tj][2], acc[ti][tj][3]);
            } else {
                float ga0 = gamma[col], ga1 = gamma[col + 1];
                float bp0 = bproj[col], bp1 = bproj[col + 1];
                {
                    size_t o = (size_t)r0 * LDC + col;
                    outp[o]     = feats[o]     + ga0 * (acc[ti][tj][0] * inv0 + bp0 * fl0);
                    outp[o + 1] = feats[o + 1] + ga1 * (acc[ti][tj][1] * inv0 + bp1 * fl0);
                }
                {
                    size_t o = (size_t)(r0 + 8) * LDC + col;
                    outp[o]     = feats[o]     + ga0 * (acc[ti][tj][2] * inv1 + bp0 * fl1);
                    outp[o + 1] = feats[o + 1] + ga1 * (acc[ti][tj][3] * inv1 + bp1 * fl1);
                }
            }
        }
    }
}

// ---------------------------------------------------------------------------
// tensor-core attention (unchanged from R8). 1 CTA per (group, head-triple).
// ---------------------------------------------------------------------------
#define ASEG 72

__global__ void __launch_bounds__(96) attn_k(const int* __restrict__ gidxw,
                                             const float* __restrict__ gmask) {
    extern __shared__ __align__(16) __nv_bfloat16 segs[];  // 9*2304
    int*   Pp = (int*)(segs + 9 * 2304);
    float* mm = (float*)(Pp + 32);

    const int tid  = threadIdx.x;
    const int lane = tid & 31;
    const int warp = tid >> 5;          // 0..2
    const int grp  = blockIdx.x >> 1;
    const int trip = blockIdx.x & 1;
    const int h0   = trip * 3;
    const int bb   = grp >> 9;          // batch

    if (tid < 32) {
        int slot = grp * KG + tid;
        int p = g_is64 ? gidxw[2 * slot] : gidxw[slot];
        p = p < 0 ? 0 : (p > 8191 ? 8191 : p);
        Pp[tid] = bb * 8192 + p;
        mm[tid] = gmask[slot];
    }
    __syncthreads();

    const unsigned sbase = (unsigned)__cvta_generic_to_shared(segs);
    for (int i = tid; i < 9 * 256; i += 96) {
        int s = i >> 8;
        int r = (i >> 3) & 31;
        int c = i & 7;
        int hh = s / 3, sec = s - 3 * hh;
        const __nv_bfloat16* src =
            g_qkv + (size_t)Pp[r] * QKVD + sec * CDIM + (h0 + hh) * DHD + c * 8;
        cp16(sbase + (unsigned)((s * 2304 + r * ASEG + c * 8) * 2), src);
    }
    asm volatile("cp.async.commit_group;\n");
    asm volatile("cp.async.wait_group 0;\n");
    __syncthreads();

    const __nv_bfloat16* Qs = segs + (warp * 3 + 0) * 2304;
    const __nv_bfloat16* Ks = segs + (warp * 3 + 1) * 2304;
    const __nv_bfloat16* Vs = segs + (warp * 3 + 2) * 2304;
    const int head = h0 + warp;

    const int g = lane >> 2, q = lane & 3;
    const int lm_r = lane & 15;
    const int lm_c = (lane >> 4) * 8;

    float sacc[2][4][4];
#pragma unroll
    for (int mi = 0; mi < 2; mi++)
#pragma unroll
        for (int nj = 0; nj < 4; nj++)
#pragma unroll
            for (int r = 0; r < 4; r++) sacc[mi][nj][r] = 0.f;

#pragma unroll
    for (int kd = 0; kd < 4; kd++) {
        unsigned aq[2][4];
#pragma unroll
        for (int mi = 0; mi < 2; mi++)
            ldsm4(aq[mi][0], aq[mi][1], aq[mi][2], aq[mi][3],
                  Qs + (mi * 16 + lm_r) * ASEG + kd * 16 + lm_c);
        unsigned bfr[4][2];
#pragma unroll
        for (int ng = 0; ng < 2; ng++) {
            unsigned x, y, z, w;
            ldsm4(x, y, z, w, Ks + (ng * 16 + lm_r) * ASEG + kd * 16 + lm_c);
            bfr[2 * ng][0]     = x;
            bfr[2 * ng][1]     = z;
            bfr[2 * ng + 1][0] = y;
            bfr[2 * ng + 1][1] = w;
        }
#pragma unroll
        for (int mi = 0; mi < 2; mi++)
#pragma unroll
            for (int nj = 0; nj < 4; nj++)
                mma16816(sacc[mi][nj], aq[mi], bfr[nj][0], bfr[nj][1]);
    }

    float bias0[4], bias1[4];
#pragma unroll
    for (int nj = 0; nj < 4; nj++) {
        bias0[nj] = mm[nj * 8 + 2 * q]     > 0.f ? 0.f : -1e9f;
        bias1[nj] = mm[nj * 8 + 2 * q + 1] > 0.f ? 0.f : -1e9f;
    }
    unsigned pa[2][2][4];
    float wr0[2], wr1[2];
    int   P0[2], P1[2];
#pragma unroll
    for (int mi = 0; mi < 2; mi++) {
        wr0[mi] = mm[mi * 16 + g];
        wr1[mi] = mm[mi * 16 + g + 8];
        P0[mi]  = Pp[mi * 16 + g];
        P1[mi]  = Pp[mi * 16 + g + 8];

        float m0 = -3e38f, m1 = -3e38f;
#pragma unroll
        for (int nj = 0; nj < 4; nj++) {
            sacc[mi][nj][0] = sacc[mi][nj][0] * 0.125f + bias0[nj];
            sacc[mi][nj][1] = sacc[mi][nj][1] * 0.125f + bias1[nj];
            sacc[mi][nj][2] = sacc[mi][nj][2] * 0.125f + bias0[nj];
            sacc[mi][nj][3] = sacc[mi][nj][3] * 0.125f + bias1[nj];
            m0 = fmaxf(m0, fmaxf(sacc[mi][nj][0], sacc[mi][nj][1]));
            m1 = fmaxf(m1, fmaxf(sacc[mi][nj][2], sacc[mi][nj][3]));
        }
        m0 = fmaxf(m0, __shfl_xor_sync(0xffffffffu, m0, 1));
        m0 = fmaxf(m0, __shfl_xor_sync(0xffffffffu, m0, 2));
        m1 = fmaxf(m1, __shfl_xor_sync(0xffffffffu, m1, 1));
        m1 = fmaxf(m1, __shfl_xor_sync(0xffffffffu, m1, 2));

        float s0 = 0.f, s1 = 0.f;
#pragma unroll
        for (int nj = 0; nj < 4; nj++) {
            sacc[mi][nj][0] = __expf(sacc[mi][nj][0] - m0);
            sacc[mi][nj][1] = __expf(sacc[mi][nj][1] - m0);
            sacc[mi][nj][2] = __expf(sacc[mi][nj][2] - m1);
            sacc[mi][nj][3] = __expf(sacc[mi][nj][3] - m1);
            s0 += sacc[mi][nj][0] + sacc[mi][nj][1];
            s1 += sacc[mi][nj][2] + sacc[mi][nj][3];
        }
        s0 += __shfl_xor_sync(0xffffffffu, s0, 1);
        s0 += __shfl_xor_sync(0xffffffffu, s0, 2);
        s1 += __shfl_xor_sync(0xffffffffu, s1, 1);
        s1 += __shfl_xor_sync(0xffffffffu, s1, 2);
        float r0 = wr0[mi] / s0;
        float r1 = wr1[mi] / s1;

#pragma unroll
        for (int ks = 0; ks < 2; ks++) {
            __nv_bfloat162 h0p = pack2(sacc[mi][2 * ks][0] * r0, sacc[mi][2 * ks][1] * r0);
            __nv_bfloat162 h1p = pack2(sacc[mi][2 * ks][2] * r1, sacc[mi][2 * ks][3] * r1);
            __nv_bfloat162 h2p = pack2(sacc[mi][2 * ks + 1][0] * r0, sacc[mi][2 * ks + 1][1] * r0);
            __nv_bfloat162 h3p = pack2(sacc[mi][2 * ks + 1][2] * r1, sacc[mi][2 * ks + 1][3] * r1);
            pa[mi][ks][0] = *(unsigned*)&h0p;
            pa[mi][ks][1] = *(unsigned*)&h1p;
            pa[mi][ks][2] = *(unsigned*)&h2p;
            pa[mi][ks][3] = *(unsigned*)&h3p;
        }
    }

    float oacc[2][8][4];
#pragma unroll
    for (int mi = 0; mi < 2; mi++)
#pragma unroll
        for (int dn = 0; dn < 8; dn++)
#pragma unroll
            for (int r = 0; r < 4; r++) oacc[mi][dn][r] = 0.f;

#pragma unroll
    for (int ks = 0; ks < 2; ks++) {
#pragma unroll
        for (int dg = 0; dg < 4; dg++) {
            unsigned x, y, z, w;
            ldsm4t(x, y, z, w, Vs + (ks * 16 + lm_r) * ASEG + dg * 16 + lm_c);
#pragma unroll
            for (int mi = 0; mi < 2; mi++) {
                mma16816(oacc[mi][2 * dg],     pa[mi][ks], x, y);
                mma16816(oacc[mi][2 * dg + 1], pa[mi][ks], z, w);
            }
        }
    }

#pragma unroll
    for (int mi = 0; mi < 2; mi++) {
        __nv_bfloat162* d0 = g_acc2 + (size_t)P0[mi] * (CDIM / 2) + head * 32 + q;
        __nv_bfloat162* d1 = g_acc2 + (size_t)P1[mi] * (CDIM / 2) + head * 32 + q;
        const bool w0 = (wr0[mi] != 0.f);
        const bool w1 = (wr1[mi] != 0.f);
#pragma unroll
        for (int dn = 0; dn < 8; dn++) {
            if (w0) {
                __nv_bfloat162 v = pack2(oacc[mi][dn][0], oacc[mi][dn][1]);
                atomicAdd(d0 + dn * 4, v);
            }
            if (w1) {
                __nv_bfloat162 v = pack2(oacc[mi][dn][2], oacc[mi][dn][3]);
                atomicAdd(d1 + dn * 4, v);
            }
        }
    }

    if (trip == 0 && tid < 32 && mm[tid] != 0.f) atomicAdd(g_cnt + Pp[tid], mm[tid]);
}

// ---------------------------------------------------------------------------
// launch — ONLY kernel launches (graph-capture safe)
// ---------------------------------------------------------------------------
extern "C" void kernel_launch(void* const* d_in, const int* in_sizes, int n_in,
                              void* d_out, int out_size) {
    const float* feats = (const float*)d_in[0];
    const int*   gidxw = (const int*)d_in[1];
    const float* gmask = (const float*)d_in[2];
    const float* wqkv  = (const float*)d_in[3];
    const float* wproj = (const float*)d_in[4];
    const float* bproj = (const float*)d_in[5];
    const float* gamma = (const float*)d_in[6];
    float*       outp  = (float*)d_out;

    const int gemm_smem = 2 * 2 * 128 * 40 * 2;            // 40960 B
    const int attn_smem = 9 * 2304 * 2 + 32 * 4 + 32 * 4;  // 41728 B

    const int nPrep = NPTS * CDIM / 8 + NPTS / 4 +
                      QKVD * CDIM / 4 + CDIM * CDIM / 4 + 1;
    k_prep<<<(nPrep + 255) / 256, 256>>>(gidxw, wqkv, wproj);

    gemm_k<false><<<dim3(QKVD / 128, NPTS / 128), 256, gemm_smem>>>(feats, nullptr, nullptr, nullptr);

    attn_k<<<NGRP * 2, 96, attn_smem>>>(gidxw, gmask);

    gemm_k<true><<<dim3(CDIM / 128, NPTS / 128), 256, gemm_smem>>>(feats, gamma, bproj, outp);
}

// round 10
// speedup vs baseline: 2.8711x; 1.0551x over previous
#include <cuda_runtime.h>
#include <cuda_bf16.h>
#include <cstdint>

// ---------------------------------------------------------------------------
// GroupLocalAttention (sm_100 baseline ISA: mma.sync + ldmatrix + cp.async):
//   0) k_prep: zero acc/cnt, convert weights to bf16, sniff idx dtype
//   1) QKV_all[p,1152] = feats[p,:] @ Wqkv^T   (gemm1: A read f32->bf16 inline)
//   2) per (group, head-triple): tensor-core attention, bf16x2 atomic scatter
//   3) out = feats + gamma*((acc/cnt) @ Wproj^T + b_proj*[cnt>0])
// GEMM mainloop: 3-stage cp.async pipeline, ONE __syncthreads per iteration,
// unpadded 64B rows + XOR swizzle (conflict-free ldmatrix), 48KB smem exactly.
// ---------------------------------------------------------------------------

#define NPTS 65536      // B * N_MAX
#define CDIM 384
#define QKVD 1152
#define NGRP 4096       // B * G
#define KG   32
#define NH   6
#define DHD  64

__device__ __align__(16) __nv_bfloat16  g_qkv[(size_t)NPTS * QKVD];
__device__ __align__(16) __nv_bfloat162 g_acc2[(size_t)NPTS * CDIM / 2];
__device__ __align__(16) float          g_cnt[NPTS];
__device__ __align__(16) __nv_bfloat16  g_wqkv_bf[QKVD * CDIM];
__device__ __align__(16) __nv_bfloat16  g_wproj_bf[CDIM * CDIM];
__device__ int g_is64;

// ---------------------------------------------------------------------------
// helpers
// ---------------------------------------------------------------------------
__device__ __forceinline__ void ldsm4(unsigned& x, unsigned& y, unsigned& z, unsigned& w,
                                      const void* p) {
    unsigned a = (unsigned)__cvta_generic_to_shared(p);
    asm volatile("ldmatrix.sync.aligned.m8n8.x4.shared.b16 {%0,%1,%2,%3}, [%4];"
                 : "=r"(x), "=r"(y), "=r"(z), "=r"(w) : "r"(a));
}
__device__ __forceinline__ void ldsm4t(unsigned& x, unsigned& y, unsigned& z, unsigned& w,
                                       const void* p) {
    unsigned a = (unsigned)__cvta_generic_to_shared(p);
    asm volatile("ldmatrix.sync.aligned.m8n8.x4.trans.shared.b16 {%0,%1,%2,%3}, [%4];"
                 : "=r"(x), "=r"(y), "=r"(z), "=r"(w) : "r"(a));
}
__device__ __forceinline__ void mma16816(float* c, const unsigned* a,
                                         unsigned b0, unsigned b1) {
    asm volatile(
        "mma.sync.aligned.m16n8k16.row.col.f32.bf16.bf16.f32 "
        "{%0,%1,%2,%3},{%4,%5,%6,%7},{%8,%9},{%0,%1,%2,%3};\n"
        : "+f"(c[0]), "+f"(c[1]), "+f"(c[2]), "+f"(c[3])
        : "r"(a[0]), "r"(a[1]), "r"(a[2]), "r"(a[3]), "r"(b0), "r"(b1));
}
__device__ __forceinline__ void cp16(unsigned dst, const void* src) {
    asm volatile("cp.async.cg.shared.global [%0], [%1], 16;\n" :: "r"(dst), "l"(src));
}
__device__ __forceinline__ __nv_bfloat162 pack2(float a, float b) {
    return __floats2bfloat162_rn(a, b);
}
// XOR swizzle: 64B rows, 4x16B chunks; chunk' = chunk ^ ((row>>1)&3)
__device__ __forceinline__ int swz16(int row, int ch) {
    return (ch ^ ((row >> 1) & 3)) << 4;   // byte offset of chunk within row
}

// ---------------------------------------------------------------------------
// fused prep: zero acc2+cnt, convert both weight matrices, sniff idx dtype
// ---------------------------------------------------------------------------
__global__ void k_prep(const int* __restrict__ w,
                       const float* __restrict__ wqkv,
                       const float* __restrict__ wproj) {
    const int nAccV = NPTS * CDIM / 8;
    const int nCntV = NPTS / 4;
    const int n1 = QKVD * CDIM / 4;
    const int n2 = CDIM * CDIM / 4;
    int i = blockIdx.x * blockDim.x + threadIdx.x;
    if (i < nAccV) {
        ((float4*)g_acc2)[i] = make_float4(0.f, 0.f, 0.f, 0.f);
    } else if (i < nAccV + nCntV) {
        ((float4*)g_cnt)[i - nAccV] = make_float4(0.f, 0.f, 0.f, 0.f);
    } else {
        int j = i - nAccV - nCntV;
        if (j < n1) {
            float4 v = ((const float4*)wqkv)[j];
            ((__nv_bfloat162*)g_wqkv_bf)[2 * j]     = __floats2bfloat162_rn(v.x, v.y);
            ((__nv_bfloat162*)g_wqkv_bf)[2 * j + 1] = __floats2bfloat162_rn(v.z, v.w);
        } else if (j < n1 + n2) {
            int k = j - n1;
            float4 v = ((const float4*)wproj)[k];
            ((__nv_bfloat162*)g_wproj_bf)[2 * k]     = __floats2bfloat162_rn(v.x, v.y);
            ((__nv_bfloat162*)g_wproj_bf)[2 * k + 1] = __floats2bfloat162_rn(v.z, v.w);
        } else if (j == n1 + n2) {
            int all0 = 1;
            for (int t = 1; t < 64; t += 2) all0 &= (w[t] == 0 || w[t] == -1);
            g_is64 = all0;
        }
    }
}

// ---------------------------------------------------------------------------
// bf16 GEMM: 128x128 CTA tile, K-tile 32, 3-stage cp.async pipeline,
// one __syncthreads per iteration, XOR-swizzled smem (64B rows).
// Stage layout: [A 128x64B][B 128x64B] = 16384 B; 3 stages = 49152 B.
// EPI=false (gemm1): A = feats f32 via LDG->cvt->STS (dist-2 reg prefetch).
// EPI=true  (gemm2): A = g_acc2 raw bf16 sums; epilogue folds 1/cnt.
// ---------------------------------------------------------------------------
#define STG_B 16384

template <bool EPI>
__global__ void __launch_bounds__(256) gemm_k(const float* __restrict__ feats,
                                              const float* __restrict__ gamma,
                                              const float* __restrict__ bproj,
                                              float* __restrict__ outp) {
    const __nv_bfloat16* __restrict__ Bw = EPI ? g_wproj_bf : g_wqkv_bf;
    constexpr int LDC = EPI ? CDIM : QKVD;

    extern __shared__ __align__(16) char smemc[];
    const unsigned sb = (unsigned)__cvta_generic_to_shared(smemc);

    const int m0 = blockIdx.y * 128;
    const int n0 = blockIdx.x * 128;
    const int tid = threadIdx.x;
    const int warp = tid >> 5, lane = tid & 31;
    const int wm = warp & 3, wn = warp >> 2;
    const int g = lane >> 2, q = lane & 3;
    const int lr  = tid >> 1;        // load row 0..127
    const int lc0 = (tid & 1) * 2;   // 16B-chunk base within 64B row
    const int lm_r = lane & 15;
    const int lm_c8 = (lane >> 4);   // 0/1: chunk offset within 16-col range

    auto load_B = [&](int kt, int slot) {
        unsigned dB = sb + slot * STG_B + 8192 + lr * 64;
        const char* gB = (const char*)(Bw + (size_t)(n0 + lr) * CDIM + kt * 32);
#pragma unroll
        for (int i = 0; i < 2; i++) {
            int ch = lc0 + i;
            cp16(dB + swz16(lr, ch), gB + ch * 16);
        }
    };
    auto load_A_cp = [&](int kt, int slot) {
        const __nv_bfloat16* A = (const __nv_bfloat16*)g_acc2;
        unsigned dA = sb + slot * STG_B + lr * 64;
        const char* gA = (const char*)(A + (size_t)(m0 + lr) * CDIM + kt * 32);
#pragma unroll
        for (int i = 0; i < 2; i++) {
            int ch = lc0 + i;
            cp16(dA + swz16(lr, ch), gA + ch * 16);
        }
    };
    float4 rA[4];
    auto ldg_A = [&](int kt) {
        const float4* src = (const float4*)(feats + (size_t)(m0 + lr) * CDIM +
                                            kt * 32 + (tid & 1) * 16);
#pragma unroll
        for (int i = 0; i < 4; i++) rA[i] = src[i];
    };
    auto sts_A = [&](int slot) {
        char* base = smemc + slot * STG_B + lr * 64;
        const float* f = (const float*)rA;
        uint4 o0, o1;
        __nv_bfloat162 h;
        h = pack2(f[0],  f[1]);  o0.x = *(unsigned*)&h;
        h = pack2(f[2],  f[3]);  o0.y = *(unsigned*)&h;
        h = pack2(f[4],  f[5]);  o0.z = *(unsigned*)&h;
        h = pack2(f[6],  f[7]);  o0.w = *(unsigned*)&h;
        h = pack2(f[8],  f[9]);  o1.x = *(unsigned*)&h;
        h = pack2(f[10], f[11]); o1.y = *(unsigned*)&h;
        h = pack2(f[12], f[13]); o1.z = *(unsigned*)&h;
        h = pack2(f[14], f[15]); o1.w = *(unsigned*)&h;
        *(uint4*)(base + swz16(lr, lc0))     = o0;
        *(uint4*)(base + swz16(lr, lc0 + 1)) = o1;
    };

    float acc[2][8][4];
#pragma unroll
    for (int ti = 0; ti < 2; ti++)
#pragma unroll
        for (int tj = 0; tj < 8; tj++)
#pragma unroll
            for (int r = 0; r < 4; r++) acc[ti][tj][r] = 0.f;

    constexpr int KT = CDIM / 32;   // 12

    // prologue: stages 0, 1
    if constexpr (EPI) {
        load_A_cp(0, 0); load_B(0, 0);
        asm volatile("cp.async.commit_group;\n");
        load_A_cp(1, 1); load_B(1, 1);
        asm volatile("cp.async.commit_group;\n");
    } else {
        ldg_A(0); sts_A(0); load_B(0, 0);
        asm volatile("cp.async.commit_group;\n");
        ldg_A(1); sts_A(1); load_B(1, 1);
        asm volatile("cp.async.commit_group;\n");
    }

    for (int kt = 0; kt < KT; kt++) {
        const int s = kt % 3;
        if constexpr (!EPI) {
            if (kt + 2 < KT) ldg_A(kt + 2);   // overlap LDG latency with mma
        }
        if (kt + 1 < KT) asm volatile("cp.async.wait_group 1;\n");
        else             asm volatile("cp.async.wait_group 0;\n");
        __syncthreads();

        const char* sA = smemc + s * STG_B;
        const char* sB = sA + 8192;
#pragma unroll
        for (int ks = 0; ks < 2; ks++) {
            const int cbase = ks * 2 + lm_c8;   // 16B chunk index 0..3
            unsigned af[2][4];
#pragma unroll
            for (int ti = 0; ti < 2; ti++) {
                int R = wm * 32 + ti * 16 + lm_r;
                ldsm4(af[ti][0], af[ti][1], af[ti][2], af[ti][3],
                      sA + R * 64 + swz16(R, cbase));
            }
            unsigned bfr[8][2];
#pragma unroll
            for (int pr2 = 0; pr2 < 4; pr2++) {
                int R = wn * 64 + pr2 * 16 + lm_r;
                unsigned x, y, z, w;
                ldsm4(x, y, z, w, sB + R * 64 + swz16(R, cbase));
                bfr[2 * pr2][0]     = x;
                bfr[2 * pr2][1]     = z;
                bfr[2 * pr2 + 1][0] = y;
                bfr[2 * pr2 + 1][1] = w;
            }
#pragma unroll
            for (int ti = 0; ti < 2; ti++)
#pragma unroll
                for (int tj = 0; tj < 8; tj++)
                    mma16816(acc[ti][tj], af[ti], bfr[tj][0], bfr[tj][1]);
        }

        if (kt + 2 < KT) {
            const int ns = (kt + 2) % 3;
            if constexpr (EPI) {
                load_A_cp(kt + 2, ns); load_B(kt + 2, ns);
            } else {
                sts_A(ns); load_B(kt + 2, ns);
            }
            asm volatile("cp.async.commit_group;\n");
        }
    }

    // epilogue
#pragma unroll
    for (int ti = 0; ti < 2; ti++) {
        int r0 = m0 + wm * 32 + ti * 16 + g;
        float inv0 = 0.f, inv1 = 0.f, fl0 = 0.f, fl1 = 0.f;
        if (EPI) {
            float c0 = g_cnt[r0], c1 = g_cnt[r0 + 8];
            inv0 = 1.f / fmaxf(c0, 1.f);
            inv1 = 1.f / fmaxf(c1, 1.f);
            fl0 = c0 > 0.5f ? 1.f : 0.f;
            fl1 = c1 > 0.5f ? 1.f : 0.f;
        }
#pragma unroll
        for (int tj = 0; tj < 8; tj++) {
            int col = n0 + wn * 64 + tj * 8 + 2 * q;
            if (!EPI) {
                *(__nv_bfloat162*)(g_qkv + (size_t)r0 * LDC + col) =
                    __floats2bfloat162_rn(acc[ti][tj][0], acc[ti][tj][1]);
                *(__nv_bfloat162*)(g_qkv + (size_t)(r0 + 8) * LDC + col) =
                    __floats2bfloat162_rn(acc[ti][tj][2], acc[ti][tj][3]);
            } else {
                float ga0 = gamma[col], ga1 = gamma[col + 1];
                float bp0 = bproj[col], bp1 = bproj[col + 1];
                {
                    size_t o = (size_t)r0 * LDC + col;
                    outp[o]     = feats[o]     + ga0 * (acc[ti][tj][0] * inv0 + bp0 * fl0);
                    outp[o + 1] = feats[o + 1] + ga1 * (acc[ti][tj][1] * inv0 + bp1 * fl0);
                }
                {
                    size_t o = (size_t)(r0 + 8) * LDC + col;
                    outp[o]     = feats[o]     + ga0 * (acc[ti][tj][2] * inv1 + bp0 * fl1);
                    outp[o + 1] = feats[o + 1] + ga1 * (acc[ti][tj][3] * inv1 + bp1 * fl1);
                }
            }
        }
    }
}

// ---------------------------------------------------------------------------
// tensor-core attention (unchanged). 1 CTA per (group, head-triple).
// ---------------------------------------------------------------------------
#define ASEG 72

__global__ void __launch_bounds__(96) attn_k(const int* __restrict__ gidxw,
                                             const float* __restrict__ gmask) {
    extern __shared__ __align__(16) __nv_bfloat16 segs[];  // 9*2304
    int*   Pp = (int*)(segs + 9 * 2304);
    float* mm = (float*)(Pp + 32);

    const int tid  = threadIdx.x;
    const int lane = tid & 31;
    const int warp = tid >> 5;
    const int grp  = blockIdx.x >> 1;
    const int trip = blockIdx.x & 1;
    const int h0   = trip * 3;
    const int bb   = grp >> 9;

    if (tid < 32) {
        int slot = grp * KG + tid;
        int p = g_is64 ? gidxw[2 * slot] : gidxw[slot];
        p = p < 0 ? 0 : (p > 8191 ? 8191 : p);
        Pp[tid] = bb * 8192 + p;
        mm[tid] = gmask[slot];
    }
    __syncthreads();

    const unsigned sbase = (unsigned)__cvta_generic_to_shared(segs);
    for (int i = tid; i < 9 * 256; i += 96) {
        int s = i >> 8;
        int r = (i >> 3) & 31;
        int c = i & 7;
        int hh = s / 3, sec = s - 3 * hh;
        const __nv_bfloat16* src =
            g_qkv + (size_t)Pp[r] * QKVD + sec * CDIM + (h0 + hh) * DHD + c * 8;
        cp16(sbase + (unsigned)((s * 2304 + r * ASEG + c * 8) * 2), src);
    }
    asm volatile("cp.async.commit_group;\n");
    asm volatile("cp.async.wait_group 0;\n");
    __syncthreads();

    const __nv_bfloat16* Qs = segs + (warp * 3 + 0) * 2304;
    const __nv_bfloat16* Ks = segs + (warp * 3 + 1) * 2304;
    const __nv_bfloat16* Vs = segs + (warp * 3 + 2) * 2304;
    const int head = h0 + warp;

    const int g = lane >> 2, q = lane & 3;
    const int lm_r = lane & 15;
    const int lm_c = (lane >> 4) * 8;

    float sacc[2][4][4];
#pragma unroll
    for (int mi = 0; mi < 2; mi++)
#pragma unroll
        for (int nj = 0; nj < 4; nj++)
#pragma unroll
            for (int r = 0; r < 4; r++) sacc[mi][nj][r] = 0.f;

#pragma unroll
    for (int kd = 0; kd < 4; kd++) {
        unsigned aq[2][4];
#pragma unroll
        for (int mi = 0; mi < 2; mi++)
            ldsm4(aq[mi][0], aq[mi][1], aq[mi][2], aq[mi][3],
                  Qs + (mi * 16 + lm_r) * ASEG + kd * 16 + lm_c);
        unsigned bfr[4][2];
#pragma unroll
        for (int ng = 0; ng < 2; ng++) {
            unsigned x, y, z, w;
            ldsm4(x, y, z, w, Ks + (ng * 16 + lm_r) * ASEG + kd * 16 + lm_c);
            bfr[2 * ng][0]     = x;
            bfr[2 * ng][1]     = z;
            bfr[2 * ng + 1][0] = y;
            bfr[2 * ng + 1][1] = w;
        }
#pragma unroll
        for (int mi = 0; mi < 2; mi++)
#pragma unroll
            for (int nj = 0; nj < 4; nj++)
                mma16816(sacc[mi][nj], aq[mi], bfr[nj][0], bfr[nj][1]);
    }

    float bias0[4], bias1[4];
#pragma unroll
    for (int nj = 0; nj < 4; nj++) {
        bias0[nj] = mm[nj * 8 + 2 * q]     > 0.f ? 0.f : -1e9f;
        bias1[nj] = mm[nj * 8 + 2 * q + 1] > 0.f ? 0.f : -1e9f;
    }
    unsigned pa[2][2][4];
    float wr0[2], wr1[2];
    int   P0[2], P1[2];
#pragma unroll
    for (int mi = 0; mi < 2; mi++) {
        wr0[mi] = mm[mi * 16 + g];
        wr1[mi] = mm[mi * 16 + g + 8];
        P0[mi]  = Pp[mi * 16 + g];
        P1[mi]  = Pp[mi * 16 + g + 8];

        float m0 = -3e38f, m1 = -3e38f;
#pragma unroll
        for (int nj = 0; nj < 4; nj++) {
            sacc[mi][nj][0] = sacc[mi][nj][0] * 0.125f + bias0[nj];
            sacc[mi][nj][1] = sacc[mi][nj][1] * 0.125f + bias1[nj];
            sacc[mi][nj][2] = sacc[mi][nj][2] * 0.125f + bias0[nj];
            sacc[mi][nj][3] = sacc[mi][nj][3] * 0.125f + bias1[nj];
            m0 = fmaxf(m0, fmaxf(sacc[mi][nj][0], sacc[mi][nj][1]));
            m1 = fmaxf(m1, fmaxf(sacc[mi][nj][2], sacc[mi][nj][3]));
        }
        m0 = fmaxf(m0, __shfl_xor_sync(0xffffffffu, m0, 1));
        m0 = fmaxf(m0, __shfl_xor_sync(0xffffffffu, m0, 2));
        m1 = fmaxf(m1, __shfl_xor_sync(0xffffffffu, m1, 1));
        m1 = fmaxf(m1, __shfl_xor_sync(0xffffffffu, m1, 2));

        float s0 = 0.f, s1 = 0.f;
#pragma unroll
        for (int nj = 0; nj < 4; nj++) {
            sacc[mi][nj][0] = __expf(sacc[mi][nj][0] - m0);
            sacc[mi][nj][1] = __expf(sacc[mi][nj][1] - m0);
            sacc[mi][nj][2] = __expf(sacc[mi][nj][2] - m1);
            sacc[mi][nj][3] = __expf(sacc[mi][nj][3] - m1);
            s0 += sacc[mi][nj][0] + sacc[mi][nj][1];
            s1 += sacc[mi][nj][2] + sacc[mi][nj][3];
        }
        s0 += __shfl_xor_sync(0xffffffffu, s0, 1);
        s0 += __shfl_xor_sync(0xffffffffu, s0, 2);
        s1 += __shfl_xor_sync(0xffffffffu, s1, 1);
        s1 += __shfl_xor_sync(0xffffffffu, s1, 2);
        float r0 = wr0[mi] / s0;
        float r1 = wr1[mi] / s1;

#pragma unroll
        for (int ks = 0; ks < 2; ks++) {
            __nv_bfloat162 h0p = pack2(sacc[mi][2 * ks][0] * r0, sacc[mi][2 * ks][1] * r0);
            __nv_bfloat162 h1p = pack2(sacc[mi][2 * ks][2] * r1, sacc[mi][2 * ks][3] * r1);
            __nv_bfloat162 h2p = pack2(sacc[mi][2 * ks + 1][0] * r0, sacc[mi][2 * ks + 1][1] * r0);
            __nv_bfloat162 h3p = pack2(sacc[mi][2 * ks + 1][2] * r1, sacc[mi][2 * ks + 1][3] * r1);
            pa[mi][ks][0] = *(unsigned*)&h0p;
            pa[mi][ks][1] = *(unsigned*)&h1p;
            pa[mi][ks][2] = *(unsigned*)&h2p;
            pa[mi][ks][3] = *(unsigned*)&h3p;
        }
    }

    float oacc[2][8][4];
#pragma unroll
    for (int mi = 0; mi < 2; mi++)
#pragma unroll
        for (int dn = 0; dn < 8; dn++)
#pragma unroll
            for (int r = 0; r < 4; r++) oacc[mi][dn][r] = 0.f;

#pragma unroll
    for (int ks = 0; ks < 2; ks++) {
#pragma unroll
        for (int dg = 0; dg < 4; dg++) {
            unsigned x, y, z, w;
            ldsm4t(x, y, z, w, Vs + (ks * 16 + lm_r) * ASEG + dg * 16 + lm_c);
#pragma unroll
            for (int mi = 0; mi < 2; mi++) {
                mma16816(oacc[mi][2 * dg],     pa[mi][ks], x, y);
                mma16816(oacc[mi][2 * dg + 1], pa[mi][ks], z, w);
            }
        }
    }

#pragma unroll
    for (int mi = 0; mi < 2; mi++) {
        __nv_bfloat162* d0 = g_acc2 + (size_t)P0[mi] * (CDIM / 2) + head * 32 + q;
        __nv_bfloat162* d1 = g_acc2 + (size_t)P1[mi] * (CDIM / 2) + head * 32 + q;
        const bool w0 = (wr0[mi] != 0.f);
        const bool w1 = (wr1[mi] != 0.f);
#pragma unroll
        for (int dn = 0; dn < 8; dn++) {
            if (w0) {
                __nv_bfloat162 v = pack2(oacc[mi][dn][0], oacc[mi][dn][1]);
                atomicAdd(d0 + dn * 4, v);
            }
            if (w1) {
                __nv_bfloat162 v = pack2(oacc[mi][dn][2], oacc[mi][dn][3]);
                atomicAdd(d1 + dn * 4, v);
            }
        }
    }

    if (trip == 0 && tid < 32 && mm[tid] != 0.f) atomicAdd(g_cnt + Pp[tid], mm[tid]);
}

// ---------------------------------------------------------------------------
// launch — ONLY kernel launches (graph-capture safe)
// ---------------------------------------------------------------------------
extern "C" void kernel_launch(void* const* d_in, const int* in_sizes, int n_in,
                              void* d_out, int out_size) {
    const float* feats = (const float*)d_in[0];
    const int*   gidxw = (const int*)d_in[1];
    const float* gmask = (const float*)d_in[2];
    const float* wqkv  = (const float*)d_in[3];
    const float* wproj = (const float*)d_in[4];
    const float* bproj = (const float*)d_in[5];
    const float* gamma = (const float*)d_in[6];
    float*       outp  = (float*)d_out;

    const int gemm_smem = 3 * STG_B;                       // 49152 B (= 48KB limit)
    const int attn_smem = 9 * 2304 * 2 + 32 * 4 + 32 * 4;  // 41728 B

    const int nPrep = NPTS * CDIM / 8 + NPTS / 4 +
                      QKVD * CDIM / 4 + CDIM * CDIM / 4 + 1;
    k_prep<<<(nPrep + 255) / 256, 256>>>(gidxw, wqkv, wproj);

    gemm_k<false><<<dim3(QKVD / 128, NPTS / 128), 256, gemm_smem>>>(feats, nullptr, nullptr, nullptr);

    attn_k<<<NGRP * 2, 96, attn_smem>>>(gidxw, gmask);

    gemm_k<true><<<dim3(CDIM / 128, NPTS / 128), 256, gemm_smem>>>(feats, gamma, bproj, outp);
}

// round 11
// speedup vs baseline: 2.9034x; 1.0112x over previous
#include <cuda_runtime.h>
#include <cuda_bf16.h>
#include <cstdint>

// ---------------------------------------------------------------------------
// GroupLocalAttention (sm_100 baseline ISA: mma.sync + ldmatrix + cp.async):
//   0) k_prep: zero acc/cnt, convert weights to bf16, sniff idx dtype
//   1) QKV_all[p,1152] = feats[p,:] @ Wqkv^T   (gemm1: A read f32->bf16 inline)
//   2) per (group, head-triple): tensor-core attention, bf16x2 atomic scatter
//   3) out = feats + gamma*((acc/cnt) @ Wproj^T + b_proj*[cnt>0])
// GEMM mainloop: FIVE-stage cp.async pipeline (wait_group 3 steady state),
// one __syncthreads per iteration, XOR-swizzled 64B rows, hoisted ldmatrix
// addresses. smem 80KB/CTA (opt-in, 2 CTAs/SM).
// ---------------------------------------------------------------------------

#define NPTS 65536      // B * N_MAX
#define CDIM 384
#define QKVD 1152
#define NGRP 4096       // B * G
#define KG   32
#define NH   6
#define DHD  64

__device__ __align__(16) __nv_bfloat16  g_qkv[(size_t)NPTS * QKVD];
__device__ __align__(16) __nv_bfloat162 g_acc2[(size_t)NPTS * CDIM / 2];
__device__ __align__(16) float          g_cnt[NPTS];
__device__ __align__(16) __nv_bfloat16  g_wqkv_bf[QKVD * CDIM];
__device__ __align__(16) __nv_bfloat16  g_wproj_bf[CDIM * CDIM];
__device__ int g_is64;

// ---------------------------------------------------------------------------
// helpers
// ---------------------------------------------------------------------------
__device__ __forceinline__ void ldsm4(unsigned& x, unsigned& y, unsigned& z, unsigned& w,
                                      unsigned a) {
    asm volatile("ldmatrix.sync.aligned.m8n8.x4.shared.b16 {%0,%1,%2,%3}, [%4];"
                 : "=r"(x), "=r"(y), "=r"(z), "=r"(w) : "r"(a));
}
__device__ __forceinline__ void ldsm4p(unsigned& x, unsigned& y, unsigned& z, unsigned& w,
                                       const void* p) {
    unsigned a = (unsigned)__cvta_generic_to_shared(p);
    asm volatile("ldmatrix.sync.aligned.m8n8.x4.shared.b16 {%0,%1,%2,%3}, [%4];"
                 : "=r"(x), "=r"(y), "=r"(z), "=r"(w) : "r"(a));
}
__device__ __forceinline__ void ldsm4t(unsigned& x, unsigned& y, unsigned& z, unsigned& w,
                                       const void* p) {
    unsigned a = (unsigned)__cvta_generic_to_shared(p);
    asm volatile("ldmatrix.sync.aligned.m8n8.x4.trans.shared.b16 {%0,%1,%2,%3}, [%4];"
                 : "=r"(x), "=r"(y), "=r"(z), "=r"(w) : "r"(a));
}
__device__ __forceinline__ void mma16816(float* c, const unsigned* a,
                                         unsigned b0, unsigned b1) {
    asm volatile(
        "mma.sync.aligned.m16n8k16.row.col.f32.bf16.bf16.f32 "
        "{%0,%1,%2,%3},{%4,%5,%6,%7},{%8,%9},{%0,%1,%2,%3};\n"
        : "+f"(c[0]), "+f"(c[1]), "+f"(c[2]), "+f"(c[3])
        : "r"(a[0]), "r"(a[1]), "r"(a[2]), "r"(a[3]), "r"(b0), "r"(b1));
}
__device__ __forceinline__ void cp16(unsigned dst, const void* src) {
    asm volatile("cp.async.cg.shared.global [%0], [%1], 16;\n" :: "r"(dst), "l"(src));
}
__device__ __forceinline__ __nv_bfloat162 pack2(float a, float b) {
    return __floats2bfloat162_rn(a, b);
}
// XOR swizzle: 64B rows, 4x16B chunks; chunk' = chunk ^ ((row>>1)&3)
__device__ __forceinline__ int swz16(int row, int ch) {
    return (ch ^ ((row >> 1) & 3)) << 4;
}

// ---------------------------------------------------------------------------
// fused prep
// ---------------------------------------------------------------------------
__global__ void k_prep(const int* __restrict__ w,
                       const float* __restrict__ wqkv,
                       const float* __restrict__ wproj) {
    const int nAccV = NPTS * CDIM / 8;
    const int nCntV = NPTS / 4;
    const int n1 = QKVD * CDIM / 4;
    const int n2 = CDIM * CDIM / 4;
    int i = blockIdx.x * blockDim.x + threadIdx.x;
    if (i < nAccV) {
        ((float4*)g_acc2)[i] = make_float4(0.f, 0.f, 0.f, 0.f);
    } else if (i < nAccV + nCntV) {
        ((float4*)g_cnt)[i - nAccV] = make_float4(0.f, 0.f, 0.f, 0.f);
    } else {
        int j = i - nAccV - nCntV;
        if (j < n1) {
            float4 v = ((const float4*)wqkv)[j];
            ((__nv_bfloat162*)g_wqkv_bf)[2 * j]     = __floats2bfloat162_rn(v.x, v.y);
            ((__nv_bfloat162*)g_wqkv_bf)[2 * j + 1] = __floats2bfloat162_rn(v.z, v.w);
        } else if (j < n1 + n2) {
            int k = j - n1;
            float4 v = ((const float4*)wproj)[k];
            ((__nv_bfloat162*)g_wproj_bf)[2 * k]     = __floats2bfloat162_rn(v.x, v.y);
            ((__nv_bfloat162*)g_wproj_bf)[2 * k + 1] = __floats2bfloat162_rn(v.z, v.w);
        } else if (j == n1 + n2) {
            int all0 = 1;
            for (int t = 1; t < 64; t += 2) all0 &= (w[t] == 0 || w[t] == -1);
            g_is64 = all0;
        }
    }
}

// ---------------------------------------------------------------------------
// bf16 GEMM: 128x128 CTA tile, K-tile 32, 5-stage cp.async pipeline.
// ---------------------------------------------------------------------------
#define STG_B 16384
#define NSTG  5

template <bool EPI>
__global__ void __launch_bounds__(256, 2) gemm_k(const float* __restrict__ feats,
                                                 const float* __restrict__ gamma,
                                                 const float* __restrict__ bproj,
                                                 float* __restrict__ outp) {
    const __nv_bfloat16* __restrict__ Bw = EPI ? g_wproj_bf : g_wqkv_bf;
    constexpr int LDC = EPI ? CDIM : QKVD;

    extern __shared__ __align__(16) char smemc[];
    const unsigned sb = (unsigned)__cvta_generic_to_shared(smemc);

    const int m0 = blockIdx.y * 128;
    const int n0 = blockIdx.x * 128;
    const int tid = threadIdx.x;
    const int warp = tid >> 5, lane = tid & 31;
    const int wm = warp & 3, wn = warp >> 2;
    const int g = lane >> 2, q = lane & 3;
    const int lr  = tid >> 1;
    const int lc0 = (tid & 1) * 2;
    const int lm_r = lane & 15;
    const int lm_c8 = (lane >> 4);

    // hoisted ldmatrix offsets (within one stage)
    unsigned offA[2][2], offB[2][4];
#pragma unroll
    for (int ks = 0; ks < 2; ks++) {
        const int cb = ks * 2 + lm_c8;
#pragma unroll
        for (int ti = 0; ti < 2; ti++) {
            int R = wm * 32 + ti * 16 + lm_r;
            offA[ks][ti] = (unsigned)(R * 64 + swz16(R, cb));
        }
#pragma unroll
        for (int pr2 = 0; pr2 < 4; pr2++) {
            int R = wn * 64 + pr2 * 16 + lm_r;
            offB[ks][pr2] = (unsigned)(8192 + R * 64 + swz16(R, cb));
        }
    }

    auto load_B = [&](int kt, int slot) {
        unsigned dB = sb + slot * STG_B + 8192 + lr * 64;
        const char* gB = (const char*)(Bw + (size_t)(n0 + lr) * CDIM + kt * 32);
#pragma unroll
        for (int i = 0; i < 2; i++) {
            int ch = lc0 + i;
            cp16(dB + swz16(lr, ch), gB + ch * 16);
        }
    };
    auto load_A_cp = [&](int kt, int slot) {
        const __nv_bfloat16* A = (const __nv_bfloat16*)g_acc2;
        unsigned dA = sb + slot * STG_B + lr * 64;
        const char* gA = (const char*)(A + (size_t)(m0 + lr) * CDIM + kt * 32);
#pragma unroll
        for (int i = 0; i < 2; i++) {
            int ch = lc0 + i;
            cp16(dA + swz16(lr, ch), gA + ch * 16);
        }
    };
    float4 rA[4];
    auto ldg_A = [&](int kt) {
        const float4* src = (const float4*)(feats + (size_t)(m0 + lr) * CDIM +
                                            kt * 32 + (tid & 1) * 16);
#pragma unroll
        for (int i = 0; i < 4; i++) rA[i] = src[i];
    };
    auto sts_A = [&](int slot) {
        char* base = smemc + slot * STG_B + lr * 64;
        const float* f = (const float*)rA;
        uint4 o0, o1;
        __nv_bfloat162 h;
        h = pack2(f[0],  f[1]);  o0.x = *(unsigned*)&h;
        h = pack2(f[2],  f[3]);  o0.y = *(unsigned*)&h;
        h = pack2(f[4],  f[5]);  o0.z = *(unsigned*)&h;
        h = pack2(f[6],  f[7]);  o0.w = *(unsigned*)&h;
        h = pack2(f[8],  f[9]);  o1.x = *(unsigned*)&h;
        h = pack2(f[10], f[11]); o1.y = *(unsigned*)&h;
        h = pack2(f[12], f[13]); o1.z = *(unsigned*)&h;
        h = pack2(f[14], f[15]); o1.w = *(unsigned*)&h;
        *(uint4*)(base + swz16(lr, lc0))     = o0;
        *(uint4*)(base + swz16(lr, lc0 + 1)) = o1;
    };

    float acc[2][8][4];
#pragma unroll
    for (int ti = 0; ti < 2; ti++)
#pragma unroll
        for (int tj = 0; tj < 8; tj++)
#pragma unroll
            for (int r = 0; r < 4; r++) acc[ti][tj][r] = 0.f;

    constexpr int KT = CDIM / 32;   // 12

    // prologue: fill stages 0..3
#pragma unroll
    for (int i = 0; i < 4; i++) {
        if constexpr (EPI) {
            load_A_cp(i, i);
        } else {
            ldg_A(i); sts_A(i);
        }
        load_B(i, i);
        asm volatile("cp.async.commit_group;\n");
    }

    for (int kt = 0; kt < KT; kt++) {
        const int s = kt % NSTG;
        if constexpr (!EPI) {
            if (kt + 4 < KT) ldg_A(kt + 4);
        }
        // pending allowed = min(3, KT-1-kt)
        if (kt < KT - 3)      asm volatile("cp.async.wait_group 3;\n");
        else if (kt == KT - 3) asm volatile("cp.async.wait_group 2;\n");
        else if (kt == KT - 2) asm volatile("cp.async.wait_group 1;\n");
        else                   asm volatile("cp.async.wait_group 0;\n");
        __syncthreads();

        const unsigned stg = sb + s * STG_B;
#pragma unroll
        for (int ks = 0; ks < 2; ks++) {
            unsigned af[2][4];
#pragma unroll
            for (int ti = 0; ti < 2; ti++)
                ldsm4(af[ti][0], af[ti][1], af[ti][2], af[ti][3], stg + offA[ks][ti]);
            unsigned bfr[8][2];
#pragma unroll
            for (int pr2 = 0; pr2 < 4; pr2++) {
                unsigned x, y, z, w;
                ldsm4(x, y, z, w, stg + offB[ks][pr2]);
                bfr[2 * pr2][0]     = x;
                bfr[2 * pr2][1]     = z;
                bfr[2 * pr2 + 1][0] = y;
                bfr[2 * pr2 + 1][1] = w;
            }
#pragma unroll
            for (int ti = 0; ti < 2; ti++)
#pragma unroll
                for (int tj = 0; tj < 8; tj++)
                    mma16816(acc[ti][tj], af[ti], bfr[tj][0], bfr[tj][1]);
        }

        if (kt + 4 < KT) {
            const int ns = (kt + 4) % NSTG;
            if constexpr (EPI) {
                load_A_cp(kt + 4, ns);
            } else {
                sts_A(ns);
            }
            load_B(kt + 4, ns);
            asm volatile("cp.async.commit_group;\n");
        }
    }

    // epilogue
#pragma unroll
    for (int ti = 0; ti < 2; ti++) {
        int r0 = m0 + wm * 32 + ti * 16 + g;
        float inv0 = 0.f, inv1 = 0.f, fl0 = 0.f, fl1 = 0.f;
        if (EPI) {
            float c0 = g_cnt[r0], c1 = g_cnt[r0 + 8];
            inv0 = 1.f / fmaxf(c0, 1.f);
            inv1 = 1.f / fmaxf(c1, 1.f);
            fl0 = c0 > 0.5f ? 1.f : 0.f;
            fl1 = c1 > 0.5f ? 1.f : 0.f;
        }
#pragma unroll
        for (int tj = 0; tj < 8; tj++) {
            int col = n0 + wn * 64 + tj * 8 + 2 * q;
            if (!EPI) {
                *(__nv_bfloat162*)(g_qkv + (size_t)r0 * LDC + col) =
                    __floats2bfloat162_rn(acc[ti][tj][0], acc[ti][tj][1]);
                *(__nv_bfloat162*)(g_qkv + (size_t)(r0 + 8) * LDC + col) =
                    __floats2bfloat162_rn(acc[ti][tj][2], acc[ti][tj][3]);
            } else {
                float ga0 = gamma[col], ga1 = gamma[col + 1];
                float bp0 = bproj[col], bp1 = bproj[col + 1];
                {
                    size_t o = (size_t)r0 * LDC + col;
                    outp[o]     = feats[o]     + ga0 * (acc[ti][tj][0] * inv0 + bp0 * fl0);
                    outp[o + 1] = feats[o + 1] + ga1 * (acc[ti][tj][1] * inv0 + bp1 * fl0);
                }
                {
                    size_t o = (size_t)(r0 + 8) * LDC + col;
                    outp[o]     = feats[o]     + ga0 * (acc[ti][tj][2] * inv1 + bp0 * fl1);
                    outp[o + 1] = feats[o + 1] + ga1 * (acc[ti][tj][3] * inv1 + bp1 * fl1);
                }
            }
        }
    }
}

// ---------------------------------------------------------------------------
// tensor-core attention (unchanged). 1 CTA per (group, head-triple).
// ---------------------------------------------------------------------------
#define ASEG 72

__global__ void __launch_bounds__(96) attn_k(const int* __restrict__ gidxw,
                                             const float* __restrict__ gmask) {
    extern __shared__ __align__(16) __nv_bfloat16 segs[];  // 9*2304
    int*   Pp = (int*)(segs + 9 * 2304);
    float* mm = (float*)(Pp + 32);

    const int tid  = threadIdx.x;
    const int lane = tid & 31;
    const int warp = tid >> 5;
    const int grp  = blockIdx.x >> 1;
    const int trip = blockIdx.x & 1;
    const int h0   = trip * 3;
    const int bb   = grp >> 9;

    if (tid < 32) {
        int slot = grp * KG + tid;
        int p = g_is64 ? gidxw[2 * slot] : gidxw[slot];
        p = p < 0 ? 0 : (p > 8191 ? 8191 : p);
        Pp[tid] = bb * 8192 + p;
        mm[tid] = gmask[slot];
    }
    __syncthreads();

    const unsigned sbase = (unsigned)__cvta_generic_to_shared(segs);
    for (int i = tid; i < 9 * 256; i += 96) {
        int s = i >> 8;
        int r = (i >> 3) & 31;
        int c = i & 7;
        int hh = s / 3, sec = s - 3 * hh;
        const __nv_bfloat16* src =
            g_qkv + (size_t)Pp[r] * QKVD + sec * CDIM + (h0 + hh) * DHD + c * 8;
        cp16(sbase + (unsigned)((s * 2304 + r * ASEG + c * 8) * 2), src);
    }
    asm volatile("cp.async.commit_group;\n");
    asm volatile("cp.async.wait_group 0;\n");
    __syncthreads();

    const __nv_bfloat16* Qs = segs + (warp * 3 + 0) * 2304;
    const __nv_bfloat16* Ks = segs + (warp * 3 + 1) * 2304;
    const __nv_bfloat16* Vs = segs + (warp * 3 + 2) * 2304;
    const int head = h0 + warp;

    const int g = lane >> 2, q = lane & 3;
    const int lm_r = lane & 15;
    const int lm_c = (lane >> 4) * 8;

    float sacc[2][4][4];
#pragma unroll
    for (int mi = 0; mi < 2; mi++)
#pragma unroll
        for (int nj = 0; nj < 4; nj++)
#pragma unroll
            for (int r = 0; r < 4; r++) sacc[mi][nj][r] = 0.f;

#pragma unroll
    for (int kd = 0; kd < 4; kd++) {
        unsigned aq[2][4];
#pragma unroll
        for (int mi = 0; mi < 2; mi++)
            ldsm4p(aq[mi][0], aq[mi][1], aq[mi][2], aq[mi][3],
                   Qs + (mi * 16 + lm_r) * ASEG + kd * 16 + lm_c);
        unsigned bfr[4][2];
#pragma unroll
        for (int ng = 0; ng < 2; ng++) {
            unsigned x, y, z, w;
            ldsm4p(x, y, z, w, Ks + (ng * 16 + lm_r) * ASEG + kd * 16 + lm_c);
            bfr[2 * ng][0]     = x;
            bfr[2 * ng][1]     = z;
            bfr[2 * ng + 1][0] = y;
            bfr[2 * ng + 1][1] = w;
        }
#pragma unroll
        for (int mi = 0; mi < 2; mi++)
#pragma unroll
            for (int nj = 0; nj < 4; nj++)
                mma16816(sacc[mi][nj], aq[mi], bfr[nj][0], bfr[nj][1]);
    }

    float bias0[4], bias1[4];
#pragma unroll
    for (int nj = 0; nj < 4; nj++) {
        bias0[nj] = mm[nj * 8 + 2 * q]     > 0.f ? 0.f : -1e9f;
        bias1[nj] = mm[nj * 8 + 2 * q + 1] > 0.f ? 0.f : -1e9f;
    }
    unsigned pa[2][2][4];
    float wr0[2], wr1[2];
    int   P0[2], P1[2];
#pragma unroll
    for (int mi = 0; mi < 2; mi++) {
        wr0[mi] = mm[mi * 16 + g];
        wr1[mi] = mm[mi * 16 + g + 8];
        P0[mi]  = Pp[mi * 16 + g];
        P1[mi]  = Pp[mi * 16 + g + 8];

        float m0 = -3e38f, m1 = -3e38f;
#pragma unroll
        for (int nj = 0; nj < 4; nj++) {
            sacc[mi][nj][0] = sacc[mi][nj][0] * 0.125f + bias0[nj];
            sacc[mi][nj][1] = sacc[mi][nj][1] * 0.125f + bias1[nj];
            sacc[mi][nj][2] = sacc[mi][nj][2] * 0.125f + bias0[nj];
            sacc[mi][nj][3] = sacc[mi][nj][3] * 0.125f + bias1[nj];
            m0 = fmaxf(m0, fmaxf(sacc[mi][nj][0], sacc[mi][nj][1]));
            m1 = fmaxf(m1, fmaxf(sacc[mi][nj][2], sacc[mi][nj][3]));
        }
        m0 = fmaxf(m0, __shfl_xor_sync(0xffffffffu, m0, 1));
        m0 = fmaxf(m0, __shfl_xor_sync(0xffffffffu, m0, 2));
        m1 = fmaxf(m1, __shfl_xor_sync(0xffffffffu, m1, 1));
        m1 = fmaxf(m1, __shfl_xor_sync(0xffffffffu, m1, 2));

        float s0 = 0.f, s1 = 0.f;
#pragma unroll
        for (int nj = 0; nj < 4; nj++) {
            sacc[mi][nj][0] = __expf(sacc[mi][nj][0] - m0);
            sacc[mi][nj][1] = __expf(sacc[mi][nj][1] - m0);
            sacc[mi][nj][2] = __expf(sacc[mi][nj][2] - m1);
            sacc[mi][nj][3] = __expf(sacc[mi][nj][3] - m1);
            s0 += sacc[mi][nj][0] + sacc[mi][nj][1];
            s1 += sacc[mi][nj][2] + sacc[mi][nj][3];
        }
        s0 += __shfl_xor_sync(0xffffffffu, s0, 1);
        s0 += __shfl_xor_sync(0xffffffffu, s0, 2);
        s1 += __shfl_xor_sync(0xffffffffu, s1, 1);
        s1 += __shfl_xor_sync(0xffffffffu, s1, 2);
        float r0 = wr0[mi] / s0;
        float r1 = wr1[mi] / s1;

#pragma unroll
        for (int ks = 0; ks < 2; ks++) {
            __nv_bfloat162 h0p = pack2(sacc[mi][2 * ks][0] * r0, sacc[mi][2 * ks][1] * r0);
            __nv_bfloat162 h1p = pack2(sacc[mi][2 * ks][2] * r1, sacc[mi][2 * ks][3] * r1);
            __nv_bfloat162 h2p = pack2(sacc[mi][2 * ks + 1][0] * r0, sacc[mi][2 * ks + 1][1] * r0);
            __nv_bfloat162 h3p = pack2(sacc[mi][2 * ks + 1][2] * r1, sacc[mi][2 * ks + 1][3] * r1);
            pa[mi][ks][0] = *(unsigned*)&h0p;
            pa[mi][ks][1] = *(unsigned*)&h1p;
            pa[mi][ks][2] = *(unsigned*)&h2p;
            pa[mi][ks][3] = *(unsigned*)&h3p;
        }
    }

    float oacc[2][8][4];
#pragma unroll
    for (int mi = 0; mi < 2; mi++)
#pragma unroll
        for (int dn = 0; dn < 8; dn++)
#pragma unroll
            for (int r = 0; r < 4; r++) oacc[mi][dn][r] = 0.f;

#pragma unroll
    for (int ks = 0; ks < 2; ks++) {
#pragma unroll
        for (int dg = 0; dg < 4; dg++) {
            unsigned x, y, z, w;
            ldsm4t(x, y, z, w, Vs + (ks * 16 + lm_r) * ASEG + dg * 16 + lm_c);
#pragma unroll
            for (int mi = 0; mi < 2; mi++) {
                mma16816(oacc[mi][2 * dg],     pa[mi][ks], x, y);
                mma16816(oacc[mi][2 * dg + 1], pa[mi][ks], z, w);
            }
        }
    }

#pragma unroll
    for (int mi = 0; mi < 2; mi++) {
        __nv_bfloat162* d0 = g_acc2 + (size_t)P0[mi] * (CDIM / 2) + head * 32 + q;
        __nv_bfloat162* d1 = g_acc2 + (size_t)P1[mi] * (CDIM / 2) + head * 32 + q;
        const bool w0 = (wr0[mi] != 0.f);
        const bool w1 = (wr1[mi] != 0.f);
#pragma unroll
        for (int dn = 0; dn < 8; dn++) {
            if (w0) {
                __nv_bfloat162 v = pack2(oacc[mi][dn][0], oacc[mi][dn][1]);
                atomicAdd(d0 + dn * 4, v);
            }
            if (w1) {
                __nv_bfloat162 v = pack2(oacc[mi][dn][2], oacc[mi][dn][3]);
                atomicAdd(d1 + dn * 4, v);
            }
        }
    }

    if (trip == 0 && tid < 32 && mm[tid] != 0.f) atomicAdd(g_cnt + Pp[tid], mm[tid]);
}

// ---------------------------------------------------------------------------
// launch (attr opt-in is host-side + idempotent; called every time —
// deterministic, no static guards, graph-capture safe)
// ---------------------------------------------------------------------------
extern "C" void kernel_launch(void* const* d_in, const int* in_sizes, int n_in,
                              void* d_out, int out_size) {
    const float* feats = (const float*)d_in[0];
    const int*   gidxw = (const int*)d_in[1];
    const float* gmask = (const float*)d_in[2];
    const float* wqkv  = (const float*)d_in[3];
    const float* wproj = (const float*)d_in[4];
    const float* bproj = (const float*)d_in[5];
    const float* gamma = (const float*)d_in[6];
    float*       outp  = (float*)d_out;

    const int gemm_smem = NSTG * STG_B;                    // 81920 B (opt-in)
    const int attn_smem = 9 * 2304 * 2 + 32 * 4 + 32 * 4;  // 41728 B

    cudaFuncSetAttribute(gemm_k<false>, cudaFuncAttributeMaxDynamicSharedMemorySize, gemm_smem);
    cudaFuncSetAttribute(gemm_k<true>,  cudaFuncAttributeMaxDynamicSharedMemorySize, gemm_smem);

    const int nPrep = NPTS * CDIM / 8 + NPTS / 4 +
                      QKVD * CDIM / 4 + CDIM * CDIM / 4 + 1;
    k_prep<<<(nPrep + 255) / 256, 256>>>(gidxw, wqkv, wproj);

    gemm_k<false><<<dim3(QKVD / 128, NPTS / 128), 256, gemm_smem>>>(feats, nullptr, nullptr, nullptr);

    attn_k<<<NGRP * 2, 96, attn_smem>>>(gidxw, gmask);

    gemm_k<true><<<dim3(CDIM / 128, NPTS / 128), 256, gemm_smem>>>(feats, gamma, bproj, outp);
}

// round 16
// speedup vs baseline: 2.9650x; 1.0212x over previous
#include <cuda_runtime.h>
#include <cuda_bf16.h>
#include <cstdint>

// ---------------------------------------------------------------------------
// GroupLocalAttention (sm_100 baseline ISA: mma.sync + ldmatrix + cp.async):
//   0) k_prep: zero acc/cnt, convert weights to bf16, sniff idx dtype
//   1) QKV_all[p,1152] = feats[p,:] @ Wqkv^T   (gemm1: A read f32->bf16 inline)
//   2) per (group, head-triple): tensor-core attention, bf16x2 atomic scatter
//      - XOR-swizzled unpadded smem (37.1KB -> 6 CTAs/SM)
//      - gather split QK-group / V-group; scores overlap V in flight
//   3) out = feats + gamma*((acc/cnt) @ Wproj^T + b_proj*[cnt>0])
// ---------------------------------------------------------------------------

#define NPTS 65536      // B * N_MAX
#define CDIM 384
#define QKVD 1152
#define NGRP 4096       // B * G
#define KG   32
#define NH   6
#define DHD  64

__device__ __align__(16) __nv_bfloat16  g_qkv[(size_t)NPTS * QKVD];
__device__ __align__(16) __nv_bfloat162 g_acc2[(size_t)NPTS * CDIM / 2];
__device__ __align__(16) float          g_cnt[NPTS];
__device__ __align__(16) __nv_bfloat16  g_wqkv_bf[QKVD * CDIM];
__device__ __align__(16) __nv_bfloat16  g_wproj_bf[CDIM * CDIM];
__device__ int g_is64;

// ---------------------------------------------------------------------------
// helpers
// ---------------------------------------------------------------------------
__device__ __forceinline__ void ldsm4(unsigned& x, unsigned& y, unsigned& z, unsigned& w,
                                      unsigned a) {
    asm volatile("ldmatrix.sync.aligned.m8n8.x4.shared.b16 {%0,%1,%2,%3}, [%4];"
                 : "=r"(x), "=r"(y), "=r"(z), "=r"(w) : "r"(a));
}
__device__ __forceinline__ void ldsm4p(unsigned& x, unsigned& y, unsigned& z, unsigned& w,
                                       const void* p) {
    unsigned a = (unsigned)__cvta_generic_to_shared(p);
    asm volatile("ldmatrix.sync.aligned.m8n8.x4.shared.b16 {%0,%1,%2,%3}, [%4];"
                 : "=r"(x), "=r"(y), "=r"(z), "=r"(w) : "r"(a));
}
__device__ __forceinline__ void ldsm4t(unsigned& x, unsigned& y, unsigned& z, unsigned& w,
                                       const void* p) {
    unsigned a = (unsigned)__cvta_generic_to_shared(p);
    asm volatile("ldmatrix.sync.aligned.m8n8.x4.trans.shared.b16 {%0,%1,%2,%3}, [%4];"
                 : "=r"(x), "=r"(y), "=r"(z), "=r"(w) : "r"(a));
}
__device__ __forceinline__ void mma16816(float* c, const unsigned* a,
                                         unsigned b0, unsigned b1) {
    asm volatile(
        "mma.sync.aligned.m16n8k16.row.col.f32.bf16.bf16.f32 "
        "{%0,%1,%2,%3},{%4,%5,%6,%7},{%8,%9},{%0,%1,%2,%3};\n"
        : "+f"(c[0]), "+f"(c[1]), "+f"(c[2]), "+f"(c[3])
        : "r"(a[0]), "r"(a[1]), "r"(a[2]), "r"(a[3]), "r"(b0), "r"(b1));
}
__device__ __forceinline__ void cp16(unsigned dst, const void* src) {
    asm volatile("cp.async.cg.shared.global [%0], [%1], 16;\n" :: "r"(dst), "l"(src));
}
__device__ __forceinline__ __nv_bfloat162 pack2(float a, float b) {
    return __floats2bfloat162_rn(a, b);
}
// GEMM swizzle: 64B rows, 4x16B chunks
__device__ __forceinline__ int swz16(int row, int ch) {
    return (ch ^ ((row >> 1) & 3)) << 4;
}
// attn swizzle: 128B rows, 8x16B chunks; chunk' = chunk ^ (row&7)
__device__ __forceinline__ int swz8(int row, int ch) {
    return (ch ^ (row & 7)) << 4;
}

// ---------------------------------------------------------------------------
// fused prep
// ---------------------------------------------------------------------------
__global__ void k_prep(const int* __restrict__ w,
                       const float* __restrict__ wqkv,
                       const float* __restrict__ wproj) {
    const int nAccV = NPTS * CDIM / 8;
    const int nCntV = NPTS / 4;
    const int n1 = QKVD * CDIM / 4;
    const int n2 = CDIM * CDIM / 4;
    int i = blockIdx.x * blockDim.x + threadIdx.x;
    if (i < nAccV) {
        ((float4*)g_acc2)[i] = make_float4(0.f, 0.f, 0.f, 0.f);
    } else if (i < nAccV + nCntV) {
        ((float4*)g_cnt)[i - nAccV] = make_float4(0.f, 0.f, 0.f, 0.f);
    } else {
        int j = i - nAccV - nCntV;
        if (j < n1) {
            float4 v = ((const float4*)wqkv)[j];
            ((__nv_bfloat162*)g_wqkv_bf)[2 * j]     = __floats2bfloat162_rn(v.x, v.y);
            ((__nv_bfloat162*)g_wqkv_bf)[2 * j + 1] = __floats2bfloat162_rn(v.z, v.w);
        } else if (j < n1 + n2) {
            int k = j - n1;
            float4 v = ((const float4*)wproj)[k];
            ((__nv_bfloat162*)g_wproj_bf)[2 * k]     = __floats2bfloat162_rn(v.x, v.y);
            ((__nv_bfloat162*)g_wproj_bf)[2 * k + 1] = __floats2bfloat162_rn(v.z, v.w);
        } else if (j == n1 + n2) {
            int all0 = 1;
            for (int t = 1; t < 64; t += 2) all0 &= (w[t] == 0 || w[t] == -1);
            g_is64 = all0;
        }
    }
}

// ---------------------------------------------------------------------------
// bf16 GEMM (unchanged from R11): 128x128 tile, 5-stage cp.async pipeline.
// ---------------------------------------------------------------------------
#define STG_B 16384
#define NSTG  5

template <bool EPI>
__global__ void __launch_bounds__(256, 2) gemm_k(const float* __restrict__ feats,
                                                 const float* __restrict__ gamma,
                                                 const float* __restrict__ bproj,
                                                 float* __restrict__ outp) {
    const __nv_bfloat16* __restrict__ Bw = EPI ? g_wproj_bf : g_wqkv_bf;
    constexpr int LDC = EPI ? CDIM : QKVD;

    extern __shared__ __align__(16) char smemc[];
    const unsigned sb = (unsigned)__cvta_generic_to_shared(smemc);

    const int m0 = blockIdx.y * 128;
    const int n0 = blockIdx.x * 128;
    const int tid = threadIdx.x;
    const int warp = tid >> 5, lane = tid & 31;
    const int wm = warp & 3, wn = warp >> 2;
    const int g = lane >> 2, q = lane & 3;
    const int lr  = tid >> 1;
    const int lc0 = (tid & 1) * 2;
    const int lm_r = lane & 15;
    const int lm_c8 = (lane >> 4);

    unsigned offA[2][2], offB[2][4];
#pragma unroll
    for (int ks = 0; ks < 2; ks++) {
        const int cb = ks * 2 + lm_c8;
#pragma unroll
        for (int ti = 0; ti < 2; ti++) {
            int R = wm * 32 + ti * 16 + lm_r;
            offA[ks][ti] = (unsigned)(R * 64 + swz16(R, cb));
        }
#pragma unroll
        for (int pr2 = 0; pr2 < 4; pr2++) {
            int R = wn * 64 + pr2 * 16 + lm_r;
            offB[ks][pr2] = (unsigned)(8192 + R * 64 + swz16(R, cb));
        }
    }

    auto load_B = [&](int kt, int slot) {
        unsigned dB = sb + slot * STG_B + 8192 + lr * 64;
        const char* gB = (const char*)(Bw + (size_t)(n0 + lr) * CDIM + kt * 32);
#pragma unroll
        for (int i = 0; i < 2; i++) {
            int ch = lc0 + i;
            cp16(dB + swz16(lr, ch), gB + ch * 16);
        }
    };
    auto load_A_cp = [&](int kt, int slot) {
        const __nv_bfloat16* A = (const __nv_bfloat16*)g_acc2;
        unsigned dA = sb + slot * STG_B + lr * 64;
        const char* gA = (const char*)(A + (size_t)(m0 + lr) * CDIM + kt * 32);
#pragma unroll
        for (int i = 0; i < 2; i++) {
            int ch = lc0 + i;
            cp16(dA + swz16(lr, ch), gA + ch * 16);
        }
    };
    float4 rA[4];
    auto ldg_A = [&](int kt) {
        const float4* src = (const float4*)(feats + (size_t)(m0 + lr) * CDIM +
                                            kt * 32 + (tid & 1) * 16);
#pragma unroll
        for (int i = 0; i < 4; i++) rA[i] = src[i];
    };
    auto sts_A = [&](int slot) {
        char* base = smemc + slot * STG_B + lr * 64;
        const float* f = (const float*)rA;
        uint4 o0, o1;
        __nv_bfloat162 h;
        h = pack2(f[0],  f[1]);  o0.x = *(unsigned*)&h;
        h = pack2(f[2],  f[3]);  o0.y = *(unsigned*)&h;
        h = pack2(f[4],  f[5]);  o0.z = *(unsigned*)&h;
        h = pack2(f[6],  f[7]);  o0.w = *(unsigned*)&h;
        h = pack2(f[8],  f[9]);  o1.x = *(unsigned*)&h;
        h = pack2(f[10], f[11]); o1.y = *(unsigned*)&h;
        h = pack2(f[12], f[13]); o1.z = *(unsigned*)&h;
        h = pack2(f[14], f[15]); o1.w = *(unsigned*)&h;
        *(uint4*)(base + swz16(lr, lc0))     = o0;
        *(uint4*)(base + swz16(lr, lc0 + 1)) = o1;
    };

    float acc[2][8][4];
#pragma unroll
    for (int ti = 0; ti < 2; ti++)
#pragma unroll
        for (int tj = 0; tj < 8; tj++)
#pragma unroll
            for (int r = 0; r < 4; r++) acc[ti][tj][r] = 0.f;

    constexpr int KT = CDIM / 32;   // 12

#pragma unroll
    for (int i = 0; i < 4; i++) {
        if constexpr (EPI) {
            load_A_cp(i, i);
        } else {
            ldg_A(i); sts_A(i);
        }
        load_B(i, i);
        asm volatile("cp.async.commit_group;\n");
    }

    for (int kt = 0; kt < KT; kt++) {
        const int s = kt % NSTG;
        if constexpr (!EPI) {
            if (kt + 4 < KT) ldg_A(kt + 4);
        }
        if (kt < KT - 3)      asm volatile("cp.async.wait_group 3;\n");
        else if (kt == KT - 3) asm volatile("cp.async.wait_group 2;\n");
        else if (kt == KT - 2) asm volatile("cp.async.wait_group 1;\n");
        else                   asm volatile("cp.async.wait_group 0;\n");
        __syncthreads();

        const unsigned stg = sb + s * STG_B;
#pragma unroll
        for (int ks = 0; ks < 2; ks++) {
            unsigned af[2][4];
#pragma unroll
            for (int ti = 0; ti < 2; ti++)
                ldsm4(af[ti][0], af[ti][1], af[ti][2], af[ti][3], stg + offA[ks][ti]);
            unsigned bfr[8][2];
#pragma unroll
            for (int pr2 = 0; pr2 < 4; pr2++) {
                unsigned x, y, z, w;
                ldsm4(x, y, z, w, stg + offB[ks][pr2]);
                bfr[2 * pr2][0]     = x;
                bfr[2 * pr2][1]     = z;
                bfr[2 * pr2 + 1][0] = y;
                bfr[2 * pr2 + 1][1] = w;
            }
#pragma unroll
            for (int ti = 0; ti < 2; ti++)
#pragma unroll
                for (int tj = 0; tj < 8; tj++)
                    mma16816(acc[ti][tj], af[ti], bfr[tj][0], bfr[tj][1]);
        }

        if (kt + 4 < KT) {
            const int ns = (kt + 4) % NSTG;
            if constexpr (EPI) {
                load_A_cp(kt + 4, ns);
            } else {
                sts_A(ns);
            }
            load_B(kt + 4, ns);
            asm volatile("cp.async.commit_group;\n");
        }
    }

#pragma unroll
    for (int ti = 0; ti < 2; ti++) {
        int r0 = m0 + wm * 32 + ti * 16 + g;
        float inv0 = 0.f, inv1 = 0.f, fl0 = 0.f, fl1 = 0.f;
        if (EPI) {
            float c0 = g_cnt[r0], c1 = g_cnt[r0 + 8];
            inv0 = 1.f / fmaxf(c0, 1.f);
            inv1 = 1.f / fmaxf(c1, 1.f);
            fl0 = c0 > 0.5f ? 1.f : 0.f;
            fl1 = c1 > 0.5f ? 1.f : 0.f;
        }
#pragma unroll
        for (int tj = 0; tj < 8; tj++) {
            int col = n0 + wn * 64 + tj * 8 + 2 * q;
            if (!EPI) {
                *(__nv_bfloat162*)(g_qkv + (size_t)r0 * LDC + col) =
                    __floats2bfloat162_rn(acc[ti][tj][0], acc[ti][tj][1]);
                *(__nv_bfloat162*)(g_qkv + (size_t)(r0 + 8) * LDC + col) =
                    __floats2bfloat162_rn(acc[ti][tj][2], acc[ti][tj][3]);
            } else {
                float ga0 = gamma[col], ga1 = gamma[col + 1];
                float bp0 = bproj[col], bp1 = bproj[col + 1];
                {
                    size_t o = (size_t)r0 * LDC + col;
                    outp[o]     = feats[o]     + ga0 * (acc[ti][tj][0] * inv0 + bp0 * fl0);
                    outp[o + 1] = feats[o + 1] + ga1 * (acc[ti][tj][1] * inv0 + bp1 * fl0);
                }
                {
                    size_t o = (size_t)(r0 + 8) * LDC + col;
                    outp[o]     = feats[o]     + ga0 * (acc[ti][tj][2] * inv1 + bp0 * fl1);
                    outp[o + 1] = feats[o + 1] + ga1 * (acc[ti][tj][3] * inv1 + bp1 * fl1);
                }
            }
        }
    }
}

// ---------------------------------------------------------------------------
// tensor-core attention. 1 CTA per (group, head-triple): 8192 CTAs x 96 thr.
// Unpadded 128B rows + XOR swizzle: smem 37.1KB -> 6 CTAs/SM.
// Gather split: segs 0-5 = Q(h0..h2),K(h0..h2) [group 0]; 6-8 = V [group 1].
// Scores+softmax run after group 0; V waited just before P@V.
// ---------------------------------------------------------------------------
__global__ void __launch_bounds__(96) attn_k(const int* __restrict__ gidxw,
                                             const float* __restrict__ gmask) {
    extern __shared__ __align__(16) __nv_bfloat16 segs[];  // 9 segs * 2048 elems
    int*   Pp = (int*)(segs + 9 * 2048);
    float* mm = (float*)(Pp + 32);

    const int tid  = threadIdx.x;
    const int lane = tid & 31;
    const int warp = tid >> 5;          // 0..2 == head within triple
    const int grp  = blockIdx.x >> 1;
    const int trip = blockIdx.x & 1;
    const int h0   = trip * 3;
    const int bb   = grp >> 9;

    if (tid < 32) {
        int slot = grp * KG + tid;
        int p = g_is64 ? gidxw[2 * slot] : gidxw[slot];
        p = p < 0 ? 0 : (p > 8191 ? 8191 : p);
        Pp[tid] = bb * 8192 + p;
        mm[tid] = gmask[slot];
    }
    __syncthreads();

    const unsigned sbase = (unsigned)__cvta_generic_to_shared(segs);
    // group 0: segs 0..5 (Q h0..h2, K h0..h2) = 1536 chunk-entries, 16/thread
    for (int j = 0; j < 16; j++) {
        int i = tid + j * 96;
        int s = i >> 8;              // 0..5
        int r = (i >> 3) & 31;
        int c = i & 7;
        int sec = s < 3 ? 0 : 1;
        int hh  = s < 3 ? s : s - 3;
        const __nv_bfloat16* src =
            g_qkv + (size_t)Pp[r] * QKVD + sec * CDIM + (h0 + hh) * DHD + c * 8;
        cp16(sbase + (unsigned)(s * 4096 + r * 128 + swz8(r, c)), src);
    }
    asm volatile("cp.async.commit_group;\n");
    // group 1: segs 6..8 (V h0..h2) = 768 entries, 8/thread
    for (int j = 0; j < 8; j++) {
        int i = tid + j * 96;
        int s = 6 + (i >> 8);        // 6..8
        int r = (i >> 3) & 31;
        int c = i & 7;
        int hh = s - 6;
        const __nv_bfloat16* src =
            g_qkv + (size_t)Pp[r] * QKVD + 2 * CDIM + (h0 + hh) * DHD + c * 8;
        cp16(sbase + (unsigned)(s * 4096 + r * 128 + swz8(r, c)), src);
    }
    asm volatile("cp.async.commit_group;\n");

    // wait for Q,K only (V still in flight)
    asm volatile("cp.async.wait_group 1;\n");
    __syncthreads();

    const __nv_bfloat16* Qs = segs + (0 + warp) * 2048;
    const __nv_bfloat16* Ks = segs + (3 + warp) * 2048;
    const __nv_bfloat16* Vs = segs + (6 + warp) * 2048;
    const int head = h0 + warp;

    const int g = lane >> 2, q = lane & 3;
    const int lm_r = lane & 15;
    const int lm_c8 = (lane >> 4);     // 0/1

    // ---- scores S = Q @ K^T ----
    float sacc[2][4][4];
#pragma unroll
    for (int mi = 0; mi < 2; mi++)
#pragma unroll
        for (int nj = 0; nj < 4; nj++)
#pragma unroll
            for (int r = 0; r < 4; r++) sacc[mi][nj][r] = 0.f;

#pragma unroll
    for (int kd = 0; kd < 4; kd++) {
        const int cb = kd * 2 + lm_c8;
        unsigned aq[2][4];
#pragma unroll
        for (int mi = 0; mi < 2; mi++) {
            int R = mi * 16 + lm_r;
            ldsm4p(aq[mi][0], aq[mi][1], aq[mi][2], aq[mi][3],
                   (const char*)Qs + R * 128 + swz8(R, cb));
        }
        unsigned bfr[4][2];
#pragma unroll
        for (int ng = 0; ng < 2; ng++) {
            int R = ng * 16 + lm_r;
            unsigned x, y, z, w;
            ldsm4p(x, y, z, w, (const char*)Ks + R * 128 + swz8(R, cb));
            bfr[2 * ng][0]     = x;
            bfr[2 * ng][1]     = z;
            bfr[2 * ng + 1][0] = y;
            bfr[2 * ng + 1][1] = w;
        }
#pragma unroll
        for (int mi = 0; mi < 2; mi++)
#pragma unroll
            for (int nj = 0; nj < 4; nj++)
                mma16816(sacc[mi][nj], aq[mi], bfr[nj][0], bfr[nj][1]);
    }

    // ---- masked softmax, fold scatter weight & 1/sum into P ----
    float bias0[4], bias1[4];
#pragma unroll
    for (int nj = 0; nj < 4; nj++) {
        bias0[nj] = mm[nj * 8 + 2 * q]     > 0.f ? 0.f : -1e9f;
        bias1[nj] = mm[nj * 8 + 2 * q + 1] > 0.f ? 0.f : -1e9f;
    }
    unsigned pa[2][2][4];
    float wr0[2], wr1[2];
    int   P0[2], P1[2];
#pragma unroll
    for (int mi = 0; mi < 2; mi++) {
        wr0[mi] = mm[mi * 16 + g];
        wr1[mi] = mm[mi * 16 + g + 8];
        P0[mi]  = Pp[mi * 16 + g];
        P1[mi]  = Pp[mi * 16 + g + 8];

        float m0 = -3e38f, m1 = -3e38f;
#pragma unroll
        for (int nj = 0; nj < 4; nj++) {
            sacc[mi][nj][0] = sacc[mi][nj][0] * 0.125f + bias0[nj];
            sacc[mi][nj][1] = sacc[mi][nj][1] * 0.125f + bias1[nj];
            sacc[mi][nj][2] = sacc[mi][nj][2] * 0.125f + bias0[nj];
            sacc[mi][nj][3] = sacc[mi][nj][3] * 0.125f + bias1[nj];
            m0 = fmaxf(m0, fmaxf(sacc[mi][nj][0], sacc[mi][nj][1]));
            m1 = fmaxf(m1, fmaxf(sacc[mi][nj][2], sacc[mi][nj][3]));
        }
        m0 = fmaxf(m0, __shfl_xor_sync(0xffffffffu, m0, 1));
        m0 = fmaxf(m0, __shfl_xor_sync(0xffffffffu, m0, 2));
        m1 = fmaxf(m1, __shfl_xor_sync(0xffffffffu, m1, 1));
        m1 = fmaxf(m1, __shfl_xor_sync(0xffffffffu, m1, 2));

        float s0 = 0.f, s1 = 0.f;
#pragma unroll
        for (int nj = 0; nj < 4; nj++) {
            sacc[mi][nj][0] = __expf(sacc[mi][nj][0] - m0);
            sacc[mi][nj][1] = __expf(sacc[mi][nj][1] - m0);
            sacc[mi][nj][2] = __expf(sacc[mi][nj][2] - m1);
            sacc[mi][nj][3] = __expf(sacc[mi][nj][3] - m1);
            s0 += sacc[mi][nj][0] + sacc[mi][nj][1];
            s1 += sacc[mi][nj][2] + sacc[mi][nj][3];
        }
        s0 += __shfl_xor_sync(0xffffffffu, s0, 1);
        s0 += __shfl_xor_sync(0xffffffffu, s0, 2);
        s1 += __shfl_xor_sync(0xffffffffu, s1, 1);
        s1 += __shfl_xor_sync(0xffffffffu, s1, 2);
        float r0 = wr0[mi] / s0;
        float r1 = wr1[mi] / s1;

#pragma unroll
        for (int ks = 0; ks < 2; ks++) {
            __nv_bfloat162 h0p = pack2(sacc[mi][2 * ks][0] * r0, sacc[mi][2 * ks][1] * r0);
            __nv_bfloat162 h1p = pack2(sacc[mi][2 * ks][2] * r1, sacc[mi][2 * ks][3] * r1);
            __nv_bfloat162 h2p = pack2(sacc[mi][2 * ks + 1][0] * r0, sacc[mi][2 * ks + 1][1] * r0);
            __nv_bfloat162 h3p = pack2(sacc[mi][2 * ks + 1][2] * r1, sacc[mi][2 * ks + 1][3] * r1);
            pa[mi][ks][0] = *(unsigned*)&h0p;
            pa[mi][ks][1] = *(unsigned*)&h1p;
            pa[mi][ks][2] = *(unsigned*)&h2p;
            pa[mi][ks][3] = *(unsigned*)&h3p;
        }
    }

    // V must be resident (all threads' group-1 copies done)
    asm volatile("cp.async.wait_group 0;\n");
    __syncthreads();

    // ---- O = P @ V  (V via ldmatrix.trans) ----
    float oacc[2][8][4];
#pragma unroll
    for (int mi = 0; mi < 2; mi++)
#pragma unroll
        for (int dn = 0; dn < 8; dn++)
#pragma unroll
            for (int r = 0; r < 4; r++) oacc[mi][dn][r] = 0.f;

#pragma unroll
    for (int ks = 0; ks < 2; ks++) {
#pragma unroll
        for (int dg = 0; dg < 4; dg++) {
            const int cb = dg * 2 + lm_c8;
            const int R = ks * 16 + lm_r;
            unsigned x, y, z, w;
            ldsm4t(x, y, z, w, (const char*)Vs + R * 128 + swz8(R, cb));
#pragma unroll
            for (int mi = 0; mi < 2; mi++) {
                mma16816(oacc[mi][2 * dg],     pa[mi][ks], x, y);
                mma16816(oacc[mi][2 * dg + 1], pa[mi][ks], z, w);
            }
        }
    }

    // ---- scatter (weights already folded into P) ----
#pragma unroll
    for (int mi = 0; mi < 2; mi++) {
        __nv_bfloat162* d0 = g_acc2 + (size_t)P0[mi] * (CDIM / 2) + head * 32 + q;
        __nv_bfloat162* d1 = g_acc2 + (size_t)P1[mi] * (CDIM / 2) + head * 32 + q;
        const bool w0 = (wr0[mi] != 0.f);
        const bool w1 = (wr1[mi] != 0.f);
#pragma unroll
        for (int dn = 0; dn < 8; dn++) {
            if (w0) {
                __nv_bfloat162 v = pack2(oacc[mi][dn][0], oacc[mi][dn][1]);
                atomicAdd(d0 + dn * 4, v);
            }
            if (w1) {
                __nv_bfloat162 v = pack2(oacc[mi][dn][2], oacc[mi][dn][3]);
                atomicAdd(d1 + dn * 4, v);
            }
        }
    }

    if (trip == 0 && tid < 32 && mm[tid] != 0.f) atomicAdd(g_cnt + Pp[tid], mm[tid]);
}

// ---------------------------------------------------------------------------
// launch (attr opt-in host-side + idempotent, called every time)
// ---------------------------------------------------------------------------
extern "C" void kernel_launch(void* const* d_in, const int* in_sizes, int n_in,
                              void* d_out, int out_size) {
    const float* feats = (const float*)d_in[0];
    const int*   gidxw = (const int*)d_in[1];
    const float* gmask = (const float*)d_in[2];
    const float* wqkv  = (const float*)d_in[3];
    const float* wproj = (const float*)d_in[4];
    const float* bproj = (const float*)d_in[5];
    const float* gamma = (const float*)d_in[6];
    float*       outp  = (float*)d_out;

    const int gemm_smem = NSTG * STG_B;                    // 81920 B (opt-in)
    const int attn_smem = 9 * 4096 + 32 * 4 + 32 * 4;      // 37120 B

    cudaFuncSetAttribute(gemm_k<false>, cudaFuncAttributeMaxDynamicSharedMemorySize, gemm_smem);
    cudaFuncSetAttribute(gemm_k<true>,  cudaFuncAttributeMaxDynamicSharedMemorySize, gemm_smem);

    const int nPrep = NPTS * CDIM / 8 + NPTS / 4 +
                      QKVD * CDIM / 4 + CDIM * CDIM / 4 + 1;
    k_prep<<<(nPrep + 255) / 256, 256>>>(gidxw, wqkv, wproj);

    gemm_k<false><<<dim3(QKVD / 128, NPTS / 128), 256, gemm_smem>>>(feats, nullptr, nullptr, nullptr);

    attn_k<<<NGRP * 2, 96, attn_smem>>>(gidxw, gmask);

    gemm_k<true><<<dim3(CDIM / 128, NPTS / 128), 256, gemm_smem>>>(feats, gamma, bproj, outp);
}

// round 17
// speedup vs baseline: 3.0682x; 1.0348x over previous
#include <cuda_runtime.h>
#include <cuda_bf16.h>
#include <cstdint>

// ---------------------------------------------------------------------------
// GroupLocalAttention (sm_100 baseline ISA: mma.sync + ldmatrix + cp.async):
//   0) k_prep: zero acc/cnt, feats->bf16, weights->bf16, sniff idx dtype
//   1) QKV_all[p,1152] = feats_bf[p,:] @ Wqkv^T  (gemm1, pure cp.async loads)
//   2) per (group, head-triple): tensor-core attention, bf16x2 atomic scatter
//   3) out = feats + gamma*((acc/cnt) @ Wproj^T + b_proj*[cnt>0])
// GEMM mainloop: K-tile 64, 3-stage cp.async pipeline (32KB/stage, 96KB smem),
// ONE __syncthreads per iteration (6 total), 128B-row XOR swizzle.
// ---------------------------------------------------------------------------

#define NPTS 65536      // B * N_MAX
#define CDIM 384
#define QKVD 1152
#define NGRP 4096       // B * G
#define KG   32
#define NH   6
#define DHD  64

__device__ __align__(16) __nv_bfloat16  g_feats_bf[(size_t)NPTS * CDIM];
__device__ __align__(16) __nv_bfloat16  g_qkv[(size_t)NPTS * QKVD];
__device__ __align__(16) __nv_bfloat162 g_acc2[(size_t)NPTS * CDIM / 2];
__device__ __align__(16) float          g_cnt[NPTS];
__device__ __align__(16) __nv_bfloat16  g_wqkv_bf[QKVD * CDIM];
__device__ __align__(16) __nv_bfloat16  g_wproj_bf[CDIM * CDIM];
__device__ int g_is64;

// ---------------------------------------------------------------------------
// helpers
// ---------------------------------------------------------------------------
__device__ __forceinline__ void ldsm4(unsigned& x, unsigned& y, unsigned& z, unsigned& w,
                                      unsigned a) {
    asm volatile("ldmatrix.sync.aligned.m8n8.x4.shared.b16 {%0,%1,%2,%3}, [%4];"
                 : "=r"(x), "=r"(y), "=r"(z), "=r"(w) : "r"(a));
}
__device__ __forceinline__ void ldsm4p(unsigned& x, unsigned& y, unsigned& z, unsigned& w,
                                       const void* p) {
    unsigned a = (unsigned)__cvta_generic_to_shared(p);
    asm volatile("ldmatrix.sync.aligned.m8n8.x4.shared.b16 {%0,%1,%2,%3}, [%4];"
                 : "=r"(x), "=r"(y), "=r"(z), "=r"(w) : "r"(a));
}
__device__ __forceinline__ void ldsm4t(unsigned& x, unsigned& y, unsigned& z, unsigned& w,
                                       const void* p) {
    unsigned a = (unsigned)__cvta_generic_to_shared(p);
    asm volatile("ldmatrix.sync.aligned.m8n8.x4.trans.shared.b16 {%0,%1,%2,%3}, [%4];"
                 : "=r"(x), "=r"(y), "=r"(z), "=r"(w) : "r"(a));
}
__device__ __forceinline__ void mma16816(float* c, const unsigned* a,
                                         unsigned b0, unsigned b1) {
    asm volatile(
        "mma.sync.aligned.m16n8k16.row.col.f32.bf16.bf16.f32 "
        "{%0,%1,%2,%3},{%4,%5,%6,%7},{%8,%9},{%0,%1,%2,%3};\n"
        : "+f"(c[0]), "+f"(c[1]), "+f"(c[2]), "+f"(c[3])
        : "r"(a[0]), "r"(a[1]), "r"(a[2]), "r"(a[3]), "r"(b0), "r"(b1));
}
__device__ __forceinline__ void cp16(unsigned dst, const void* src) {
    asm volatile("cp.async.cg.shared.global [%0], [%1], 16;\n" :: "r"(dst), "l"(src));
}
__device__ __forceinline__ __nv_bfloat162 pack2(float a, float b) {
    return __floats2bfloat162_rn(a, b);
}
// 128B rows, 8x16B chunks; chunk' = chunk ^ (row&7)  (conflict-free ldmatrix)
__device__ __forceinline__ int swz8(int row, int ch) {
    return (ch ^ (row & 7)) << 4;
}

// ---------------------------------------------------------------------------
// fused prep: feats->bf16, zero acc2+cnt, weights->bf16, sniff idx dtype
// ---------------------------------------------------------------------------
__global__ void k_prep(const int* __restrict__ w,
                       const float* __restrict__ feats,
                       const float* __restrict__ wqkv,
                       const float* __restrict__ wproj) {
    const int nF4   = NPTS * CDIM / 4;    // feats conversion (float4 units)
    const int nAccV = NPTS * CDIM / 8;
    const int nCntV = NPTS / 4;
    const int n1 = QKVD * CDIM / 4;
    const int n2 = CDIM * CDIM / 4;
    int i = blockIdx.x * blockDim.x + threadIdx.x;
    if (i < nF4) {
        float4 v = ((const float4*)feats)[i];
        ((__nv_bfloat162*)g_feats_bf)[2 * i]     = __floats2bfloat162_rn(v.x, v.y);
        ((__nv_bfloat162*)g_feats_bf)[2 * i + 1] = __floats2bfloat162_rn(v.z, v.w);
    } else if (i < nF4 + nAccV) {
        ((float4*)g_acc2)[i - nF4] = make_float4(0.f, 0.f, 0.f, 0.f);
    } else if (i < nF4 + nAccV + nCntV) {
        ((float4*)g_cnt)[i - nF4 - nAccV] = make_float4(0.f, 0.f, 0.f, 0.f);
    } else {
        int j = i - nF4 - nAccV - nCntV;
        if (j < n1) {
            float4 v = ((const float4*)wqkv)[j];
            ((__nv_bfloat162*)g_wqkv_bf)[2 * j]     = __floats2bfloat162_rn(v.x, v.y);
            ((__nv_bfloat162*)g_wqkv_bf)[2 * j + 1] = __floats2bfloat162_rn(v.z, v.w);
        } else if (j < n1 + n2) {
            int k = j - n1;
            float4 v = ((const float4*)wproj)[k];
            ((__nv_bfloat162*)g_wproj_bf)[2 * k]     = __floats2bfloat162_rn(v.x, v.y);
            ((__nv_bfloat162*)g_wproj_bf)[2 * k + 1] = __floats2bfloat162_rn(v.z, v.w);
        } else if (j == n1 + n2) {
            int all0 = 1;
            for (int t = 1; t < 64; t += 2) all0 &= (w[t] == 0 || w[t] == -1);
            g_is64 = all0;
        }
    }
}

// ---------------------------------------------------------------------------
// bf16 GEMM: 128x128 CTA tile, K-tile 64, 3-stage cp.async pipeline,
// one __syncthreads per iteration (KT=6), 128B-row swz8 swizzle.
// Stage: [A 128x128B][B 128x128B] = 32768 B; 3 stages = 98304 B (opt-in).
// EPI=false (gemm1): A = g_feats_bf -> C = g_qkv (bf16)
// EPI=true  (gemm2): A = g_acc2 raw bf16 sums; epilogue folds 1/cnt.
// ---------------------------------------------------------------------------
#define STG_B 32768
#define NSTG  3

template <bool EPI>
__global__ void __launch_bounds__(256, 2) gemm_k(const float* __restrict__ feats,
                                                 const float* __restrict__ gamma,
                                                 const float* __restrict__ bproj,
                                                 float* __restrict__ outp) {
    const __nv_bfloat16* __restrict__ Aw = EPI ? (const __nv_bfloat16*)g_acc2 : g_feats_bf;
    const __nv_bfloat16* __restrict__ Bw = EPI ? g_wproj_bf : g_wqkv_bf;
    constexpr int LDC = EPI ? CDIM : QKVD;

    extern __shared__ __align__(16) char smemc[];
    const unsigned sb = (unsigned)__cvta_generic_to_shared(smemc);

    const int m0 = blockIdx.y * 128;
    const int n0 = blockIdx.x * 128;
    const int tid = threadIdx.x;
    const int warp = tid >> 5, lane = tid & 31;
    const int wm = warp & 3, wn = warp >> 2;
    const int g = lane >> 2, q = lane & 3;
    const int lr  = tid >> 1;        // load row 0..127
    const int lc0 = (tid & 1) * 4;   // 16B-chunk base (8 chunks per 128B row)
    const int lm_r = lane & 15;
    const int lm_c8 = (lane >> 4);

    // hoisted ldmatrix offsets for ks=0,1 ; ks=2,3 = same ^ 64 (chunk+4)
    unsigned offA[2][2], offB[2][4];
#pragma unroll
    for (int ks = 0; ks < 2; ks++) {
        const int cb = ks * 2 + lm_c8;        // chunk 0..3
#pragma unroll
        for (int ti = 0; ti < 2; ti++) {
            int R = wm * 32 + ti * 16 + lm_r;
            offA[ks][ti] = (unsigned)(R * 128 + swz8(R, cb));
        }
#pragma unroll
        for (int pr2 = 0; pr2 < 4; pr2++) {
            int R = wn * 64 + pr2 * 16 + lm_r;
            offB[ks][pr2] = (unsigned)(16384 + R * 128 + swz8(R, cb));
        }
    }

    auto load_AB = [&](int kt, int slot) {
        unsigned dA = sb + slot * STG_B + lr * 128;
        unsigned dB = dA + 16384;
        const char* gA = (const char*)(Aw + (size_t)(m0 + lr) * CDIM + kt * 64);
        const char* gB = (const char*)(Bw + (size_t)(n0 + lr) * CDIM + kt * 64);
#pragma unroll
        for (int i = 0; i < 4; i++) {
            int ch = lc0 + i;
            cp16(dA + swz8(lr, ch), gA + ch * 16);
            cp16(dB + swz8(lr, ch), gB + ch * 16);
        }
    };

    float acc[2][8][4];
#pragma unroll
    for (int ti = 0; ti < 2; ti++)
#pragma unroll
        for (int tj = 0; tj < 8; tj++)
#pragma unroll
            for (int r = 0; r < 4; r++) acc[ti][tj][r] = 0.f;

    constexpr int KT = CDIM / 64;   // 6

    // prologue: stages 0, 1
    load_AB(0, 0);
    asm volatile("cp.async.commit_group;\n");
    load_AB(1, 1);
    asm volatile("cp.async.commit_group;\n");

    for (int kt = 0; kt < KT; kt++) {
        const int s = kt % NSTG;
        if (kt < KT - 1) asm volatile("cp.async.wait_group 1;\n");
        else             asm volatile("cp.async.wait_group 0;\n");
        __syncthreads();

        const unsigned stg = sb + s * STG_B;
#pragma unroll
        for (int ks = 0; ks < 4; ks++) {
            const unsigned x4 = (unsigned)((ks & 2) << 5);   // 0 or 64
            unsigned af[2][4];
#pragma unroll
            for (int ti = 0; ti < 2; ti++)
                ldsm4(af[ti][0], af[ti][1], af[ti][2], af[ti][3],
                      stg + (offA[ks & 1][ti] ^ x4));
            unsigned bfr[8][2];
#pragma unroll
            for (int pr2 = 0; pr2 < 4; pr2++) {
                unsigned x, y, z, w;
                ldsm4(x, y, z, w, stg + (offB[ks & 1][pr2] ^ x4));
                bfr[2 * pr2][0]     = x;
                bfr[2 * pr2][1]     = z;
                bfr[2 * pr2 + 1][0] = y;
                bfr[2 * pr2 + 1][1] = w;
            }
#pragma unroll
            for (int ti = 0; ti < 2; ti++)
#pragma unroll
                for (int tj = 0; tj < 8; tj++)
                    mma16816(acc[ti][tj], af[ti], bfr[tj][0], bfr[tj][1]);
        }

        if (kt + 2 < KT) {
            load_AB(kt + 2, (kt + 2) % NSTG);
            asm volatile("cp.async.commit_group;\n");
        }
    }

    // epilogue
#pragma unroll
    for (int ti = 0; ti < 2; ti++) {
        int r0 = m0 + wm * 32 + ti * 16 + g;
        float inv0 = 0.f, inv1 = 0.f, fl0 = 0.f, fl1 = 0.f;
        if (EPI) {
            float c0 = g_cnt[r0], c1 = g_cnt[r0 + 8];
            inv0 = 1.f / fmaxf(c0, 1.f);
            inv1 = 1.f / fmaxf(c1, 1.f);
            fl0 = c0 > 0.5f ? 1.f : 0.f;
            fl1 = c1 > 0.5f ? 1.f : 0.f;
        }
#pragma unroll
        for (int tj = 0; tj < 8; tj++) {
            int col = n0 + wn * 64 + tj * 8 + 2 * q;
            if (!EPI) {
                *(__nv_bfloat162*)(g_qkv + (size_t)r0 * LDC + col) =
                    __floats2bfloat162_rn(acc[ti][tj][0], acc[ti][tj][1]);
                *(__nv_bfloat162*)(g_qkv + (size_t)(r0 + 8) * LDC + col) =
                    __floats2bfloat162_rn(acc[ti][tj][2], acc[ti][tj][3]);
            } else {
                float ga0 = gamma[col], ga1 = gamma[col + 1];
                float bp0 = bproj[col], bp1 = bproj[col + 1];
                {
                    size_t o = (size_t)r0 * LDC + col;
                    outp[o]     = feats[o]     + ga0 * (acc[ti][tj][0] * inv0 + bp0 * fl0);
                    outp[o + 1] = feats[o + 1] + ga1 * (acc[ti][tj][1] * inv0 + bp1 * fl0);
                }
                {
                    size_t o = (size_t)(r0 + 8) * LDC + col;
                    outp[o]     = feats[o]     + ga0 * (acc[ti][tj][2] * inv1 + bp0 * fl1);
                    outp[o + 1] = feats[o + 1] + ga1 * (acc[ti][tj][3] * inv1 + bp1 * fl1);
                }
            }
        }
    }
}

// ---------------------------------------------------------------------------
// tensor-core attention (unchanged from R16). 1 CTA per (group, head-triple).
// ---------------------------------------------------------------------------
__global__ void __launch_bounds__(96) attn_k(const int* __restrict__ gidxw,
                                             const float* __restrict__ gmask) {
    extern __shared__ __align__(16) __nv_bfloat16 segs[];  // 9 segs * 2048 elems
    int*   Pp = (int*)(segs + 9 * 2048);
    float* mm = (float*)(Pp + 32);

    const int tid  = threadIdx.x;
    const int lane = tid & 31;
    const int warp = tid >> 5;          // 0..2 == head within triple
    const int grp  = blockIdx.x >> 1;
    const int trip = blockIdx.x & 1;
    const int h0   = trip * 3;
    const int bb   = grp >> 9;

    if (tid < 32) {
        int slot = grp * KG + tid;
        int p = g_is64 ? gidxw[2 * slot] : gidxw[slot];
        p = p < 0 ? 0 : (p > 8191 ? 8191 : p);
        Pp[tid] = bb * 8192 + p;
        mm[tid] = gmask[slot];
    }
    __syncthreads();

    const unsigned sbase = (unsigned)__cvta_generic_to_shared(segs);
    for (int j = 0; j < 16; j++) {
        int i = tid + j * 96;
        int s = i >> 8;              // 0..5
        int r = (i >> 3) & 31;
        int c = i & 7;
        int sec = s < 3 ? 0 : 1;
        int hh  = s < 3 ? s : s - 3;
        const __nv_bfloat16* src =
            g_qkv + (size_t)Pp[r] * QKVD + sec * CDIM + (h0 + hh) * DHD + c * 8;
        cp16(sbase + (unsigned)(s * 4096 + r * 128 + swz8(r, c)), src);
    }
    asm volatile("cp.async.commit_group;\n");
    for (int j = 0; j < 8; j++) {
        int i = tid + j * 96;
        int s = 6 + (i >> 8);        // 6..8
        int r = (i >> 3) & 31;
        int c = i & 7;
        int hh = s - 6;
        const __nv_bfloat16* src =
            g_qkv + (size_t)Pp[r] * QKVD + 2 * CDIM + (h0 + hh) * DHD + c * 8;
        cp16(sbase + (unsigned)(s * 4096 + r * 128 + swz8(r, c)), src);
    }
    asm volatile("cp.async.commit_group;\n");

    asm volatile("cp.async.wait_group 1;\n");
    __syncthreads();

    const __nv_bfloat16* Qs = segs + (0 + warp) * 2048;
    const __nv_bfloat16* Ks = segs + (3 + warp) * 2048;
    const __nv_bfloat16* Vs = segs + (6 + warp) * 2048;
    const int head = h0 + warp;

    const int g = lane >> 2, q = lane & 3;
    const int lm_r = lane & 15;
    const int lm_c8 = (lane >> 4);

    float sacc[2][4][4];
#pragma unroll
    for (int mi = 0; mi < 2; mi++)
#pragma unroll
        for (int nj = 0; nj < 4; nj++)
#pragma unroll
            for (int r = 0; r < 4; r++) sacc[mi][nj][r] = 0.f;

#pragma unroll
    for (int kd = 0; kd < 4; kd++) {
        const int cb = kd * 2 + lm_c8;
        unsigned aq[2][4];
#pragma unroll
        for (int mi = 0; mi < 2; mi++) {
            int R = mi * 16 + lm_r;
            ldsm4p(aq[mi][0], aq[mi][1], aq[mi][2], aq[mi][3],
                   (const char*)Qs + R * 128 + swz8(R, cb));
        }
        unsigned bfr[4][2];
#pragma unroll
        for (int ng = 0; ng < 2; ng++) {
            int R = ng * 16 + lm_r;
            unsigned x, y, z, w;
            ldsm4p(x, y, z, w, (const char*)Ks + R * 128 + swz8(R, cb));
            bfr[2 * ng][0]     = x;
            bfr[2 * ng][1]     = z;
            bfr[2 * ng + 1][0] = y;
            bfr[2 * ng + 1][1] = w;
        }
#pragma unroll
        for (int mi = 0; mi < 2; mi++)
#pragma unroll
            for (int nj = 0; nj < 4; nj++)
                mma16816(sacc[mi][nj], aq[mi], bfr[nj][0], bfr[nj][1]);
    }

    float bias0[4], bias1[4];
#pragma unroll
    for (int nj = 0; nj < 4; nj++) {
        bias0[nj] = mm[nj * 8 + 2 * q]     > 0.f ? 0.f : -1e9f;
        bias1[nj] = mm[nj * 8 + 2 * q + 1] > 0.f ? 0.f : -1e9f;
    }
    unsigned pa[2][2][4];
    float wr0[2], wr1[2];
    int   P0[2], P1[2];
#pragma unroll
    for (int mi = 0; mi < 2; mi++) {
        wr0[mi] = mm[mi * 16 + g];
        wr1[mi] = mm[mi * 16 + g + 8];
        P0[mi]  = Pp[mi * 16 + g];
        P1[mi]  = Pp[mi * 16 + g + 8];

        float m0 = -3e38f, m1 = -3e38f;
#pragma unroll
        for (int nj = 0; nj < 4; nj++) {
            sacc[mi][nj][0] = sacc[mi][nj][0] * 0.125f + bias0[nj];
            sacc[mi][nj][1] = sacc[mi][nj][1] * 0.125f + bias1[nj];
            sacc[mi][nj][2] = sacc[mi][nj][2] * 0.125f + bias0[nj];
            sacc[mi][nj][3] = sacc[mi][nj][3] * 0.125f + bias1[nj];
            m0 = fmaxf(m0, fmaxf(sacc[mi][nj][0], sacc[mi][nj][1]));
            m1 = fmaxf(m1, fmaxf(sacc[mi][nj][2], sacc[mi][nj][3]));
        }
        m0 = fmaxf(m0, __shfl_xor_sync(0xffffffffu, m0, 1));
        m0 = fmaxf(m0, __shfl_xor_sync(0xffffffffu, m0, 2));
        m1 = fmaxf(m1, __shfl_xor_sync(0xffffffffu, m1, 1));
        m1 = fmaxf(m1, __shfl_xor_sync(0xffffffffu, m1, 2));

        float s0 = 0.f, s1 = 0.f;
#pragma unroll
        for (int nj = 0; nj < 4; nj++) {
            sacc[mi][nj][0] = __expf(sacc[mi][nj][0] - m0);
            sacc[mi][nj][1] = __expf(sacc[mi][nj][1] - m0);
            sacc[mi][nj][2] = __expf(sacc[mi][nj][2] - m1);
            sacc[mi][nj][3] = __expf(sacc[mi][nj][3] - m1);
            s0 += sacc[mi][nj][0] + sacc[mi][nj][1];
            s1 += sacc[mi][nj][2] + sacc[mi][nj][3];
        }
        s0 += __shfl_xor_sync(0xffffffffu, s0, 1);
        s0 += __shfl_xor_sync(0xffffffffu, s0, 2);
        s1 += __shfl_xor_sync(0xffffffffu, s1, 1);
        s1 += __shfl_xor_sync(0xffffffffu, s1, 2);
        float r0 = wr0[mi] / s0;
        float r1 = wr1[mi] / s1;

#pragma unroll
        for (int ks = 0; ks < 2; ks++) {
            __nv_bfloat162 h0p = pack2(sacc[mi][2 * ks][0] * r0, sacc[mi][2 * ks][1] * r0);
            __nv_bfloat162 h1p = pack2(sacc[mi][2 * ks][2] * r1, sacc[mi][2 * ks][3] * r1);
            __nv_bfloat162 h2p = pack2(sacc[mi][2 * ks + 1][0] * r0, sacc[mi][2 * ks + 1][1] * r0);
            __nv_bfloat162 h3p = pack2(sacc[mi][2 * ks + 1][2] * r1, sacc[mi][2 * ks + 1][3] * r1);
            pa[mi][ks][0] = *(unsigned*)&h0p;
            pa[mi][ks][1] = *(unsigned*)&h1p;
            pa[mi][ks][2] = *(unsigned*)&h2p;
            pa[mi][ks][3] = *(unsigned*)&h3p;
        }
    }

    asm volatile("cp.async.wait_group 0;\n");
    __syncthreads();

    float oacc[2][8][4];
#pragma unroll
    for (int mi = 0; mi < 2; mi++)
#pragma unroll
        for (int dn = 0; dn < 8; dn++)
#pragma unroll
            for (int r = 0; r < 4; r++) oacc[mi][dn][r] = 0.f;

#pragma unroll
    for (int ks = 0; ks < 2; ks++) {
#pragma unroll
        for (int dg = 0; dg < 4; dg++) {
            const int cb = dg * 2 + lm_c8;
            const int R = ks * 16 + lm_r;
            unsigned x, y, z, w;
            ldsm4t(x, y, z, w, (const char*)Vs + R * 128 + swz8(R, cb));
#pragma unroll
            for (int mi = 0; mi < 2; mi++) {
                mma16816(oacc[mi][2 * dg],     pa[mi][ks], x, y);
                mma16816(oacc[mi][2 * dg + 1], pa[mi][ks], z, w);
            }
        }
    }

#pragma unroll
    for (int mi = 0; mi < 2; mi++) {
        __nv_bfloat162* d0 = g_acc2 + (size_t)P0[mi] * (CDIM / 2) + head * 32 + q;
        __nv_bfloat162* d1 = g_acc2 + (size_t)P1[mi] * (CDIM / 2) + head * 32 + q;
        const bool w0 = (wr0[mi] != 0.f);
        const bool w1 = (wr1[mi] != 0.f);
#pragma unroll
        for (int dn = 0; dn < 8; dn++) {
            if (w0) {
                __nv_bfloat162 v = pack2(oacc[mi][dn][0], oacc[mi][dn][1]);
                atomicAdd(d0 + dn * 4, v);
            }
            if (w1) {
                __nv_bfloat162 v = pack2(oacc[mi][dn][2], oacc[mi][dn][3]);
                atomicAdd(d1 + dn * 4, v);
            }
        }
    }

    if (trip == 0 && tid < 32 && mm[tid] != 0.f) atomicAdd(g_cnt + Pp[tid], mm[tid]);
}

// ---------------------------------------------------------------------------
// launch (attr opt-in host-side + idempotent, called every time)
// ---------------------------------------------------------------------------
extern "C" void kernel_launch(void* const* d_in, const int* in_sizes, int n_in,
                              void* d_out, int out_size) {
    const float* feats = (const float*)d_in[0];
    const int*   gidxw = (const int*)d_in[1];
    const float* gmask = (const float*)d_in[2];
    const float* wqkv  = (const float*)d_in[3];
    const float* wproj = (const float*)d_in[4];
    const float* bproj = (const float*)d_in[5];
    const float* gamma = (const float*)d_in[6];
    float*       outp  = (float*)d_out;

    const int gemm_smem = NSTG * STG_B;                    // 98304 B (opt-in)
    const int attn_smem = 9 * 4096 + 32 * 4 + 32 * 4;      // 37120 B

    cudaFuncSetAttribute(gemm_k<false>, cudaFuncAttributeMaxDynamicSharedMemorySize, gemm_smem);
    cudaFuncSetAttribute(gemm_k<true>,  cudaFuncAttributeMaxDynamicSharedMemorySize, gemm_smem);

    const int nPrep = NPTS * CDIM / 4 + NPTS * CDIM / 8 + NPTS / 4 +
                      QKVD * CDIM / 4 + CDIM * CDIM / 4 + 1;
    k_prep<<<(nPrep + 255) / 256, 256>>>(gidxw, feats, wqkv, wproj);

    gemm_k<false><<<dim3(QKVD / 128, NPTS / 128), 256, gemm_smem>>>(feats, nullptr, nullptr, nullptr);

    attn_k<<<NGRP * 2, 96, attn_smem>>>(gidxw, gmask);

    gemm_k<true><<<dim3(CDIM / 128, NPTS / 128), 256, gemm_smem>>>(feats, gamma, bproj, outp);
}